// round 13
// baseline (speedup 1.0000x reference)
#include <cuda_runtime.h>
#include <cuda_fp16.h>
#include <math.h>
#include <stdint.h>

#define B_   4
#define L_   4096
#define E_   1024
#define H_   16
#define HD_  64
#define M_   (B_*L_)    // 16384 rows
#define BH_  (B_*H_)    // 64 heads
#define EPS_ 1e-4f
#define KTOT 1024       // plain 1-term fp16
#define NCHUNK 16       // kv l-chunks
#define KVCH (L_/NCHUNK) // 256

// ---------------- scratch (no allocations allowed) ----------------
__device__ __half g_x2[(size_t)M_*KTOT];
__device__ __half g_attn2[(size_t)M_*KTOT];
__device__ __half g_w2[4][(size_t)E_*KTOT];
__device__ __half g_qh[(size_t)M_*E_];
__device__ __half g_kh[(size_t)M_*E_];
__device__ __half g_vh[(size_t)M_*E_];
__device__ __half g_kvph[(size_t)NCHUNK*BH_*128*HD_];   // fp16 partials [chunk][head][d'(128)][m(64)]
__device__ float g_ksump[NCHUNK*BH_*128];
__device__ float g_ksum[BH_*128];
__device__ __half g_kvt[(size_t)BH_*128*64];  // [head][slab(2)][m(64)][d(64)] fp16

// ================= PTX helpers (sm_80-generic only!) =================
__device__ __forceinline__ uint32_t smem_u32(const void* p) {
    uint32_t a;
    asm("{ .reg .u64 t; cvta.to.shared.u64 t, %1; cvt.u32.u64 %0, t; }" : "=r"(a) : "l"(p));
    return a;
}
__device__ __forceinline__ void cp_async16(uint32_t saddr, const void* gaddr) {
    asm volatile("cp.async.cg.shared.global [%0], [%1], 16;" :: "r"(saddr), "l"(gaddr) : "memory");
}
__device__ __forceinline__ void cp_commit() {
    asm volatile("cp.async.commit_group;" ::: "memory");
}
template<int N> __device__ __forceinline__ void cp_wait_group() {
    asm volatile("cp.async.wait_group %0;" :: "n"(N) : "memory");
}
__device__ __forceinline__ void ldmatrix_x4(uint32_t* r, uint32_t addr) {
    asm volatile("ldmatrix.sync.aligned.m8n8.x4.shared.b16 {%0,%1,%2,%3}, [%4];"
        : "=r"(r[0]), "=r"(r[1]), "=r"(r[2]), "=r"(r[3]) : "r"(addr));
}
__device__ __forceinline__ void ldmatrix_x4_trans(uint32_t* r, uint32_t addr) {
    asm volatile("ldmatrix.sync.aligned.m8n8.x4.trans.shared.b16 {%0,%1,%2,%3}, [%4];"
        : "=r"(r[0]), "=r"(r[1]), "=r"(r[2]), "=r"(r[3]) : "r"(addr));
}
__device__ __forceinline__ void mma_fp16(float* c, const uint32_t* a, uint32_t b0, uint32_t b1) {
    asm volatile("mma.sync.aligned.m16n8k16.row.col.f32.f16.f16.f32 "
        "{%0,%1,%2,%3}, {%4,%5,%6,%7}, {%8,%9}, {%0,%1,%2,%3};"
        : "+f"(c[0]), "+f"(c[1]), "+f"(c[2]), "+f"(c[3])
        : "r"(a[0]), "r"(a[1]), "r"(a[2]), "r"(a[3]), "r"(b0), "r"(b1));
}
__device__ __forceinline__ uint32_t swz(uint32_t off) { return off ^ ((off >> 3) & 0x70); }

// address for ldmatrix.x4.trans over a [row][64 halves] swizzled tile
__device__ __forceinline__ uint32_t trans_addr(uint32_t base, int kk, int colhalf, int lane) {
    int mat = lane >> 3, r = lane & 7;
    int lrow = kk * 16 + ((mat & 2) << 2) + r;
    int cb = colhalf * 2 + ((mat & 1) << 4);
    return base + swz((uint32_t)lrow * 128 + cb);
}

// ================= merged fp32 -> fp16 convert (x + 4 weights) =================
// blocks [0,16384): x ; [16384, 16384+4*1024): weights
__global__ void convert_all(const float* __restrict__ x,
                            const float* __restrict__ w0, const float* __restrict__ w1,
                            const float* __restrict__ w2s, const float* __restrict__ w3,
                            __half* __restrict__ x2, __half* __restrict__ wout)
{
    int bid = blockIdx.x;
    const float* in;
    __half* out;
    int idx;
    if (bid < 16384) {
        in = x; out = g_x2;   // == x2
        idx = bid * 256 + threadIdx.x;
    } else {
        int wb = bid - 16384;
        int seg = wb >> 10;
        in = (seg == 0) ? w0 : (seg == 1) ? w1 : (seg == 2) ? w2s : w3;
        out = wout + (size_t)seg * E_ * KTOT;
        idx = (wb & 1023) * 256 + threadIdx.x;
    }
    float4 v = *(const float4*)&in[(size_t)idx * 4];
    union { __half b[4]; uint2 u; } Hh;
    Hh.b[0] = __float2half_rn(v.x);
    Hh.b[1] = __float2half_rn(v.y);
    Hh.b[2] = __float2half_rn(v.z);
    Hh.b[3] = __float2half_rn(v.w);
    *(uint2*)&out[(size_t)idx * 4] = Hh.u;
}

// ================= HMMA GEMM =================
// Tile 128x128x64, 8 warps, warp tile 64x32, mma.sync m16n8k16.
#define GBM 128
#define GBN 128
#define SLAB 64                 // fp16 K per slab = 128 bytes per row
#define NSLAB (KTOT/SLAB)       // 16
#define NSTG 3
#define AB_BYTES (GBM*128)      // 16384 (A tile == B tile size)
#define STG_BYTES (2*AB_BYTES)  // 32768
#define GEMM_DSMEM (NSTG*STG_BYTES + 1024)

__device__ __forceinline__ void gemm_issue_loads(
    const __half* ga, const __half* gw,
    uint32_t base, int slab, int buf, int t)
{
    int k0 = slab * SLAB;
    uint32_t stA = base + buf * STG_BYTES;
    uint32_t stW = stA + AB_BYTES;
    const __half* gak = ga + k0;
    const __half* gwk = gw + k0;
    #pragma unroll
    for (int j = 0; j < 4; j++) {
        int i = t + j * 256;            // 0..1023
        int row = i >> 3, c = i & 7;
        cp_async16(stA + swz(row * 128 + c * 16), gak + (size_t)row * KTOT + c * 8);
    }
    #pragma unroll
    for (int j = 0; j < 4; j++) {
        int i = t + j * 256;
        int row = i >> 3, c = i & 7;
        cp_async16(stW + swz(row * 128 + c * 16), gwk + (size_t)row * KTOT + c * 8);
    }
    cp_commit();
}

struct GemmFrag { float acc[4][4][4]; };

__device__ __forceinline__ void gemm_mainloop(
    const __half* ga, const __half* gw, uint32_t base, int t, GemmFrag& F)
{
    const int wid = t >> 5, lane = t & 31;
    const int wm = wid >> 2;
    const int wn = wid & 3;
    #pragma unroll
    for (int mi = 0; mi < 4; mi++)
        #pragma unroll
        for (int ni = 0; ni < 4; ni++)
            #pragma unroll
            for (int r = 0; r < 4; r++) F.acc[mi][ni][r] = 0.f;

    #pragma unroll
    for (int s = 0; s < NSTG - 1; s++) gemm_issue_loads(ga, gw, base, s, s, t);

    const int lrow = lane & 15;
    const int lhalf = (lane >> 4) * 16;

    for (int i = 0; i < NSLAB; i++) {
        cp_wait_group<NSTG - 2>();
        __syncthreads();
        if (i + NSTG - 1 < NSLAB)
            gemm_issue_loads(ga, gw, base, i + NSTG - 1, (i + NSTG - 1) % NSTG, t);
        else
            cp_commit();

        uint32_t sA = base + (i % NSTG) * STG_BYTES;
        uint32_t sB = sA + AB_BYTES;

        #pragma unroll
        for (int kk = 0; kk < 4; kk++) {
            uint32_t a[4][4], b[2][4];
            #pragma unroll
            for (int mi = 0; mi < 4; mi++) {
                uint32_t off = (uint32_t)(wm * 64 + mi * 16 + lrow) * 128 + kk * 32 + lhalf;
                ldmatrix_x4(a[mi], sA + swz(off));
            }
            #pragma unroll
            for (int nb = 0; nb < 2; nb++) {
                uint32_t off = (uint32_t)(wn * 32 + nb * 16 + lrow) * 128 + kk * 32 + lhalf;
                ldmatrix_x4(b[nb], sB + swz(off));
            }
            #pragma unroll
            for (int mi = 0; mi < 4; mi++)
                #pragma unroll
                for (int ni = 0; ni < 4; ni++) {
                    int nb = ni >> 1, hi = ni & 1;
                    mma_fp16(F.acc[mi][ni], a[mi], b[nb][hi], b[nb][hi + 2]);
                }
        }
        __syncthreads();
    }
}

// fp32 epilogue (Wo output)
__device__ __forceinline__ void gemm_epilogue_f32(
    GemmFrag& F, const float* bias, float* C, int bm, int cn, int t)
{
    const int wid = t >> 5, lane = t & 31;
    const int wm = wid >> 2, wn = wid & 3;
    const int qrow = lane >> 2;
    const int qcol = (lane & 3) * 2;
    #pragma unroll
    for (int mi = 0; mi < 4; mi++) {
        int row0 = bm + wm * 64 + mi * 16 + qrow;
        #pragma unroll
        for (int ni = 0; ni < 4; ni++) {
            int col = cn + wn * 32 + ni * 8 + qcol;
            float2 bb = *(const float2*)&bias[col];
            *(float2*)&C[(size_t)row0 * E_ + col] =
                make_float2(F.acc[mi][ni][0] + bb.x, F.acc[mi][ni][1] + bb.y);
            *(float2*)&C[(size_t)(row0 + 8) * E_ + col] =
                make_float2(F.acc[mi][ni][2] + bb.x, F.acc[mi][ni][3] + bb.y);
        }
    }
}

// fp16 epilogue (q/k/v outputs)
__device__ __forceinline__ void gemm_epilogue_f16(
    GemmFrag& F, const float* bias, __half* C, int bm, int cn, bool relu, int t)
{
    const int wid = t >> 5, lane = t & 31;
    const int wm = wid >> 2, wn = wid & 3;
    const int qrow = lane >> 2;
    const int qcol = (lane & 3) * 2;
    #pragma unroll
    for (int mi = 0; mi < 4; mi++) {
        int row0 = bm + wm * 64 + mi * 16 + qrow;
        #pragma unroll
        for (int ni = 0; ni < 4; ni++) {
            int col = cn + wn * 32 + ni * 8 + qcol;
            float2 bb = *(const float2*)&bias[col];
            float v0 = F.acc[mi][ni][0] + bb.x;
            float v1 = F.acc[mi][ni][1] + bb.y;
            float v2 = F.acc[mi][ni][2] + bb.x;
            float v3 = F.acc[mi][ni][3] + bb.y;
            if (relu) {
                v0 = fmaxf(v0, 0.f); v1 = fmaxf(v1, 0.f);
                v2 = fmaxf(v2, 0.f); v3 = fmaxf(v3, 0.f);
            }
            __half2 p01 = __floats2half2_rn(v0, v1);
            __half2 p23 = __floats2half2_rn(v2, v3);
            *(__half2*)&C[(size_t)row0 * E_ + col]       = p01;
            *(__half2*)&C[(size_t)(row0 + 8) * E_ + col] = p23;
        }
    }
}

// Merged Q/K/V projection: W2all = [Wq2; Wk2; Wv2] rows 0..3071
__global__ __launch_bounds__(256, 2)
void gemm_qkv(const __half* __restrict__ A2, const __half* __restrict__ W2all,
              const float* __restrict__ bq, const float* __restrict__ bk,
              const float* __restrict__ bv,
              __half* __restrict__ qp, __half* __restrict__ kp, __half* __restrict__ vp)
{
    extern __shared__ char dsm[];
    const int t = threadIdx.x;
    const int bm = blockIdx.y * GBM;
    const int bnG = blockIdx.x * GBN;          // 0..2944
    const int seg = bnG >> 10;                 // 0=q 1=k 2=v
    const int cn = bnG & 1023;

    uint32_t base = (smem_u32(dsm) + 1023u) & ~1023u;
    const __half* ga = A2 + (size_t)bm * KTOT;
    const __half* gw = W2all + (size_t)bnG * KTOT;

    GemmFrag F;
    gemm_mainloop(ga, gw, base, t, F);

    const float* bias = (seg == 0) ? bq : (seg == 1) ? bk : bv;
    __half* C = (seg == 0) ? qp : (seg == 1) ? kp : vp;
    gemm_epilogue_f16(F, bias, C, bm, cn, seg < 2, t);
}

// Single-output GEMM (used for Wo)
__global__ __launch_bounds__(256, 2)
void gemm_mma(const __half* __restrict__ A2, const __half* __restrict__ W2,
              const float* __restrict__ bias, float* __restrict__ C)
{
    extern __shared__ char dsm[];
    const int t = threadIdx.x;
    const int bm = blockIdx.y * GBM;
    const int bn = blockIdx.x * GBN;

    uint32_t base = (smem_u32(dsm) + 1023u) & ~1023u;
    const __half* ga = A2 + (size_t)bm * KTOT;
    const __half* gw = W2 + (size_t)bn * KTOT;

    GemmFrag F;
    gemm_mainloop(ga, gw, base, t, F);
    gemm_epilogue_f32(F, bias, C, bm, bn, t);
}

// ================= kv via HMMA (ldmatrix.trans, zero staging) =================
__global__ __launch_bounds__(256, 2)
void kv_hmma(const __half* __restrict__ k, const __half* __restrict__ v)
{
    __shared__ __align__(16) __half Ksm[2][64 * 64];
    __shared__ __align__(16) __half Vsm[2][64 * 64];
    __shared__ __half2 wsin[KVCH / 2], wcos[KVCH / 2];   // 128 pairs each

    const int t = threadIdx.x;
    const int wid = t >> 5, lane = t & 31;
    const int head = blockIdx.x, chunk = blockIdx.y;
    const int b = head / H_, h = head % H_;

    if (t < KVCH / 2) {
        int l0 = chunk * KVCH + t * 2;
        float s0, c0, s1, c1;
        sincosf((float)M_PI * 0.5f * (float)(l0 + 1) / (float)L_, &s0, &c0);
        sincosf((float)M_PI * 0.5f * (float)(l0 + 2) / (float)L_, &s1, &c1);
        wsin[t] = __floats2half2_rn(s0, s1);
        wcos[t] = __floats2half2_rn(c0, c1);
    }

    const __half* kbase = k + ((size_t)(b * L_ + chunk * KVCH)) * E_ + h * HD_;
    const __half* vbase = v + ((size_t)(b * L_ + chunk * KVCH)) * E_ + h * HD_;

    auto issue = [&](int slab, int buf) {
        uint32_t sK = smem_u32(Ksm[buf]);
        uint32_t sV = smem_u32(Vsm[buf]);
        #pragma unroll
        for (int j = 0; j < 4; j++) {
            int i = t + j * 256;            // 0..1023: first 512 = k, next = v
            int idx = i & 511;
            int row = idx >> 3, c = idx & 7;
            const __half* src = ((i >> 9) ? vbase : kbase)
                              + (size_t)(slab * 64 + row) * E_ + c * 8;
            uint32_t dst = ((i >> 9) ? sV : sK) + swz((uint32_t)row * 128 + c * 16);
            cp_async16(dst, src);
        }
        cp_commit();
    };

    float acc[9][4];
    #pragma unroll
    for (int n8 = 0; n8 < 9; n8++)
        #pragma unroll
        for (int r = 0; r < 4; r++) acc[n8][r] = 0.f;

    issue(0, 0);
    const uint32_t ONES = 0x3C003C00u;
    const int d0 = (wid & 3) * 16;

    #pragma unroll
    for (int slab = 0; slab < KVCH / 64; slab++) {     // 4
        if (slab + 1 < KVCH / 64) {
            issue(slab + 1, (slab + 1) & 1);
            cp_wait_group<1>();
        } else {
            cp_wait_group<0>();
        }
        __syncthreads();
        uint32_t sK = smem_u32(Ksm[slab & 1]);
        uint32_t sV = smem_u32(Vsm[slab & 1]);
        const __half2* wsel = (wid < 4) ? wsin : wcos;
        #pragma unroll
        for (int kk = 0; kk < 4; kk++) {
            uint32_t a[4], bf[4][4];
            ldmatrix_x4_trans(a, trans_addr(sK, kk, d0, lane));
            #pragma unroll
            for (int nb = 0; nb < 4; nb++)
                ldmatrix_x4_trans(bf[nb], trans_addr(sV, kk, nb * 16, lane));
            __half2 w0 = wsel[slab * 32 + kk * 8 + (lane & 3)];
            __half2 w1 = wsel[slab * 32 + kk * 8 + (lane & 3) + 4];
            __half2* ah = (__half2*)a;
            ah[0] = __hmul2(ah[0], w0);
            ah[1] = __hmul2(ah[1], w0);
            ah[2] = __hmul2(ah[2], w1);
            ah[3] = __hmul2(ah[3], w1);
            #pragma unroll
            for (int n8 = 0; n8 < 8; n8++)
                mma_fp16(acc[n8], a, bf[n8 >> 1][n8 & 1], bf[n8 >> 1][(n8 & 1) + 2]);
            mma_fp16(acc[8], a, ONES, ONES);
        }
        __syncthreads();
    }

    // epilogue: fp16 partial kv + fp32 ksum partial
    const int qr = lane >> 2, qc = (lane & 3) * 2;
    __half* kvout = g_kvph + ((size_t)(chunk * BH_ + head)) * 128 * HD_;
    #pragma unroll
    for (int n8 = 0; n8 < 8; n8++) {
        int col = n8 * 8 + qc;
        __half2 p01 = __floats2half2_rn(acc[n8][0], acc[n8][1]);
        __half2 p23 = __floats2half2_rn(acc[n8][2], acc[n8][3]);
        *(__half2*)&kvout[(wid * 16 + qr) * HD_ + col]     = p01;
        *(__half2*)&kvout[(wid * 16 + qr + 8) * HD_ + col] = p23;
    }
    if ((lane & 3) == 0) {
        g_ksump[(chunk * BH_ + head) * 128 + wid * 16 + qr]     = acc[8][0];
        g_ksump[(chunk * BH_ + head) * 128 + wid * 16 + qr + 8] = acc[8][2];
    }
}

// Reduce fp16 partials; emit transposed fp16 kv with coalesced writes.
// grid (BH_, 8): slice = 16 d' rows (1024 elems). smem transpose buffer.
__global__ __launch_bounds__(256)
void kv_reduce()
{
    __shared__ float buf[16][65];
    const int head = blockIdx.x, slice = blockIdx.y;
    const int t = threadIdx.x;

    // accumulate: coalesced reads over e = d'*64 + m
    #pragma unroll
    for (int j = 0; j < 4; j++) {
        int el = t + j * 256;               // 0..1023 local
        int e = slice * 1024 + el;
        float s = 0.f;
        #pragma unroll
        for (int c = 0; c < NCHUNK; c++)
            s += __half2float(g_kvph[((size_t)(c * BH_ + head)) * 128 * HD_ + e]);
        buf[el >> 6][el & 63] = s;          // [d_local][m]
    }
    __syncthreads();

    // write coalesced: g_kvt[head][slab][m][d&63]; slice covers d' = slice*16..+15
    const int d_base = slice * 16;
    const int slab = d_base >> 6;
    const int dmod = d_base & 63;
    __half* outp = g_kvt + (((size_t)head * 2 + slab) * 64) * 64;
    #pragma unroll
    for (int j = 0; j < 4; j++) {
        int o = t + j * 256;                // 0..1023
        int m = o >> 4, dlo = o & 15;
        outp[m * 64 + dmod + dlo] = __float2half_rn(buf[dlo][m]);
    }

    if (slice == 0 && t < 128) {
        float s = 0.f;
        #pragma unroll
        for (int c = 0; c < NCHUNK; c++)
            s += g_ksump[(c * BH_ + head) * 128 + t];
        g_ksum[head * 128 + t] = s;
    }
}

// ================= attn via HMMA =================
// A = q_ fp16 1-term (2 slabs of k64), B = kvt single-term (2 slabs).
// Passes: (A0,B0)(A1,B1) = sum over d' of q_ * kv.
#define ATT_A_SM 32768            // 2 slabs * 128 rows * 128B
#define ATT_B_SM 16384            // 2 slabs * 64 rows * 128B
#define ATT_DSMEM (ATT_A_SM + ATT_B_SM + 128)

__global__ __launch_bounds__(256, 2)
void attn_hmma(const __half* __restrict__ q)
{
    extern __shared__ char dsm[];
    __shared__ float ss[128], cs[128], zs[128], ks_s[128];

    const int t = threadIdx.x;
    const int wid = t >> 5, lane = t & 31;
    const int ltile = blockIdx.x;           // 0..31
    const int head  = blockIdx.y;           // 0..63
    const int b = head / H_, h = head % H_;

    char* sm = (char*)((((uintptr_t)dsm) + 127) & ~(uintptr_t)127);
    uint32_t sA = smem_u32(sm);
    uint32_t sB = sA + ATT_A_SM;

    if (t < 128) {
        int l = ltile * 128 + t;
        float ang = (float)M_PI * 0.5f * (float)(l + 1) / (float)L_;
        sincosf(ang, &ss[t], &cs[t]);
        ks_s[t] = g_ksum[head * 128 + t];
    }

    {
        const __half* kvt = g_kvt + (size_t)head * 128 * 64;
        #pragma unroll
        for (int j = 0; j < 4; j++) {
            int i = t + j * 256;            // 0..1023 16B chunks
            int row = i >> 3, c = i & 7;    // 128 rows of 64 halves
            cp_async16(sB + swz((uint32_t)row * 128 + c * 16),
                       kvt + row * 64 + c * 8);
        }
        cp_commit();
    }
    __syncthreads();

    {
        const int l_loc = t >> 1;           // 0..127
        const int halfsel = t & 1;
        int lg = ltile * 128 + l_loc;
        const __half* qrow = q + ((size_t)(b * L_ + lg)) * E_ + h * HD_;
        float w = halfsel ? cs[l_loc] : ss[l_loc];
        float zpart = 0.f;
        char* aw = sm + halfsel * 16384;    // slab halfsel
        #pragma unroll 4
        for (int it = 0; it < 32; it++) {
            int dp = halfsel * 64 + 2 * it;
            float2 qq = __half22float2(*(const __half2*)&qrow[dp & 63]);
            float f0 = w * qq.x, f1 = w * qq.y;
            zpart += f0 * ks_s[dp] + f1 * ks_s[dp + 1];
            __half2 Hp = __floats2half2_rn(f0, f1);
            uint32_t off = swz((uint32_t)l_loc * 128 + (dp & 63) * 2);
            *(uint32_t*)(aw + off) = *(uint32_t*)&Hp;
        }
        zpart += __shfl_xor_sync(0xffffffffu, zpart, 1);
        if (!halfsel) zs[l_loc] = 1.f / fmaxf(zpart, EPS_);
    }

    cp_wait_group<0>();
    __syncthreads();

    const int wm = wid & 1;
    const int wn = wid >> 1;
    const int lrow = lane & 15;
    const int lhalf = (lane >> 4) * 16;

    float acc[4][2][4];
    #pragma unroll
    for (int mi = 0; mi < 4; mi++)
        #pragma unroll
        for (int hi = 0; hi < 2; hi++)
            #pragma unroll
            for (int r = 0; r < 4; r++) acc[mi][hi][r] = 0.f;

    #pragma unroll
    for (int p = 0; p < 2; p++) {
        uint32_t a_s = sA + p * 16384;
        uint32_t b_s = sB + p * 8192;
        #pragma unroll
        for (int kk = 0; kk < 4; kk++) {
            uint32_t a[4][4], bfr[4];
            #pragma unroll
            for (int mi = 0; mi < 4; mi++) {
                uint32_t off = (uint32_t)(wm * 64 + mi * 16 + lrow) * 128 + kk * 32 + lhalf;
                ldmatrix_x4(a[mi], a_s + swz(off));
            }
            {
                uint32_t off = (uint32_t)(wn * 16 + lrow) * 128 + kk * 32 + lhalf;
                ldmatrix_x4(bfr, b_s + swz(off));
            }
            #pragma unroll
            for (int mi = 0; mi < 4; mi++)
                #pragma unroll
                for (int hi = 0; hi < 2; hi++)
                    mma_fp16(acc[mi][hi], a[mi], bfr[hi], bfr[hi + 2]);
        }
    }

    const int qr = lane >> 2;
    const int qc = (lane & 3) * 2;
    #pragma unroll
    for (int mi = 0; mi < 4; mi++) {
        #pragma unroll
        for (int hi = 0; hi < 2; hi++) {
            #pragma unroll
            for (int r = 0; r < 2; r++) {
                int lloc = wm * 64 + mi * 16 + qr + r * 8;
                int n = wn * 16 + hi * 8 + qc;
                float z = zs[lloc];
                __half2 Hp = __floats2half2_rn(acc[mi][hi][r * 2 + 0] * z,
                                               acc[mi][hi][r * 2 + 1] * z);
                __half* ob = g_attn2 + ((size_t)(b * L_ + ltile * 128 + lloc)) * KTOT
                           + h * HD_ + n;
                *(uint32_t*)(ob) = *(uint32_t*)&Hp;
            }
        }
    }
}

// ================= launcher =================
extern "C" void kernel_launch(void* const* d_in, const int* in_sizes, int n_in,
                              void* d_out, int out_size)
{
    const float* x  = (const float*)d_in[0];
    const float* Wq = (const float*)d_in[1];
    const float* bq = (const float*)d_in[2];
    const float* Wk = (const float*)d_in[3];
    const float* bk = (const float*)d_in[4];
    const float* Wv = (const float*)d_in[5];
    const float* bv = (const float*)d_in[6];
    const float* Wo = (const float*)d_in[7];
    const float* bo = (const float*)d_in[8];
    float* out = (float*)d_out;

    __half *x2, *attn2, *w2, *qh, *kh, *vh;
    cudaGetSymbolAddress((void**)&x2,    g_x2);
    cudaGetSymbolAddress((void**)&attn2, g_attn2);
    cudaGetSymbolAddress((void**)&w2,    g_w2);
    cudaGetSymbolAddress((void**)&qh,    g_qh);
    cudaGetSymbolAddress((void**)&kh,    g_kh);
    cudaGetSymbolAddress((void**)&vh,    g_vh);
    __half* w2o = w2 + (size_t)3 * E_ * KTOT;

    cudaFuncSetAttribute(gemm_mma,  cudaFuncAttributeMaxDynamicSharedMemorySize, GEMM_DSMEM);
    cudaFuncSetAttribute(gemm_qkv,  cudaFuncAttributeMaxDynamicSharedMemorySize, GEMM_DSMEM);
    cudaFuncSetAttribute(attn_hmma, cudaFuncAttributeMaxDynamicSharedMemorySize, ATT_DSMEM);

    // one merged conversion launch: x + 4 weights
    convert_all<<<16384 + 4096, 256>>>(x, Wq, Wk, Wv, Wo, x2, w2);

    // merged QKV projection (fp16 outputs)
    gemm_qkv<<<dim3(3 * E_ / GBN, M_ / GBM), 256, GEMM_DSMEM>>>(
        x2, w2, bq, bk, bv, qh, kh, vh);

    kv_hmma<<<dim3(BH_, NCHUNK), 256>>>(kh, vh);
    kv_reduce<<<dim3(BH_, 8), 256>>>();
    attn_hmma<<<dim3(32, BH_), 256, ATT_DSMEM>>>(qh);

    gemm_mma<<<dim3(E_ / GBN, M_ / GBM), 256, GEMM_DSMEM>>>(attn2, w2o, bo, out);
}

// round 14
// speedup vs baseline: 1.5050x; 1.5050x over previous
#include <cuda_runtime.h>
#include <cuda_fp16.h>
#include <math.h>
#include <stdint.h>

#define B_   4
#define L_   4096
#define E_   1024
#define H_   16
#define HD_  64
#define M_   (B_*L_)    // 16384 rows
#define BH_  (B_*H_)    // 64 heads
#define EPS_ 1e-4f
#define KTOT 1024       // plain 1-term fp16
#define NCHUNK 16       // kv l-chunks
#define KVCH (L_/NCHUNK) // 256

// ---------------- scratch (no allocations allowed) ----------------
__device__ __half g_x2[(size_t)M_*KTOT];
__device__ __half g_attn2[(size_t)M_*KTOT];
__device__ __half g_w2[4][(size_t)E_*KTOT];
__device__ __half g_qh[(size_t)M_*E_];
__device__ __half g_kh[(size_t)M_*E_];
__device__ __half g_vh[(size_t)M_*E_];
__device__ float g_kvp[(size_t)NCHUNK*BH_*128*HD_];
__device__ float g_ksump[NCHUNK*BH_*128];
__device__ float g_ksum[BH_*128];
__device__ __half g_kvt[(size_t)BH_*128*64];  // [head][slab(2)][m(64)][d(64)] fp16

// ================= PTX helpers (sm_80-generic only!) =================
__device__ __forceinline__ uint32_t smem_u32(const void* p) {
    uint32_t a;
    asm("{ .reg .u64 t; cvta.to.shared.u64 t, %1; cvt.u32.u64 %0, t; }" : "=r"(a) : "l"(p));
    return a;
}
__device__ __forceinline__ void cp_async16(uint32_t saddr, const void* gaddr) {
    asm volatile("cp.async.cg.shared.global [%0], [%1], 16;" :: "r"(saddr), "l"(gaddr) : "memory");
}
__device__ __forceinline__ void cp_commit() {
    asm volatile("cp.async.commit_group;" ::: "memory");
}
template<int N> __device__ __forceinline__ void cp_wait_group() {
    asm volatile("cp.async.wait_group %0;" :: "n"(N) : "memory");
}
__device__ __forceinline__ void ldmatrix_x4(uint32_t* r, uint32_t addr) {
    asm volatile("ldmatrix.sync.aligned.m8n8.x4.shared.b16 {%0,%1,%2,%3}, [%4];"
        : "=r"(r[0]), "=r"(r[1]), "=r"(r[2]), "=r"(r[3]) : "r"(addr));
}
__device__ __forceinline__ void ldmatrix_x4_trans(uint32_t* r, uint32_t addr) {
    asm volatile("ldmatrix.sync.aligned.m8n8.x4.trans.shared.b16 {%0,%1,%2,%3}, [%4];"
        : "=r"(r[0]), "=r"(r[1]), "=r"(r[2]), "=r"(r[3]) : "r"(addr));
}
__device__ __forceinline__ void mma_fp16(float* c, const uint32_t* a, uint32_t b0, uint32_t b1) {
    asm volatile("mma.sync.aligned.m16n8k16.row.col.f32.f16.f16.f32 "
        "{%0,%1,%2,%3}, {%4,%5,%6,%7}, {%8,%9}, {%0,%1,%2,%3};"
        : "+f"(c[0]), "+f"(c[1]), "+f"(c[2]), "+f"(c[3])
        : "r"(a[0]), "r"(a[1]), "r"(a[2]), "r"(a[3]), "r"(b0), "r"(b1));
}
__device__ __forceinline__ uint32_t swz(uint32_t off) { return off ^ ((off >> 3) & 0x70); }

// address for ldmatrix.x4.trans over a [row][64 halves] swizzled tile
__device__ __forceinline__ uint32_t trans_addr(uint32_t base, int kk, int colhalf, int lane) {
    int mat = lane >> 3, r = lane & 7;
    int lrow = kk * 16 + ((mat & 2) << 2) + r;
    int cb = colhalf * 2 + ((mat & 1) << 4);
    return base + swz((uint32_t)lrow * 128 + cb);
}

// ================= merged fp32 -> fp16 convert (x + 4 weights) =================
// blocks [0,16384): x ; [16384, 16384+4*1024): weights
__global__ void convert_all(const float* __restrict__ x,
                            const float* __restrict__ w0, const float* __restrict__ w1,
                            const float* __restrict__ w2s, const float* __restrict__ w3,
                            __half* __restrict__ x2, __half* __restrict__ wout)
{
    int bid = blockIdx.x;
    const float* in;
    __half* out;
    int idx;
    if (bid < 16384) {
        in = x; out = g_x2;   // == x2
        idx = bid * 256 + threadIdx.x;
    } else {
        int wb = bid - 16384;
        int seg = wb >> 10;
        in = (seg == 0) ? w0 : (seg == 1) ? w1 : (seg == 2) ? w2s : w3;
        out = wout + (size_t)seg * E_ * KTOT;
        idx = (wb & 1023) * 256 + threadIdx.x;
    }
    float4 v = *(const float4*)&in[(size_t)idx * 4];
    union { __half b[4]; uint2 u; } Hh;
    Hh.b[0] = __float2half_rn(v.x);
    Hh.b[1] = __float2half_rn(v.y);
    Hh.b[2] = __float2half_rn(v.z);
    Hh.b[3] = __float2half_rn(v.w);
    *(uint2*)&out[(size_t)idx * 4] = Hh.u;
}

// ================= HMMA GEMM =================
// Tile 128x128x64, 8 warps, warp tile 64x32, mma.sync m16n8k16.
#define GBM 128
#define GBN 128
#define SLAB 64                 // fp16 K per slab = 128 bytes per row
#define NSLAB (KTOT/SLAB)       // 16
#define NSTG 3
#define AB_BYTES (GBM*128)      // 16384 (A tile == B tile size)
#define STG_BYTES (2*AB_BYTES)  // 32768
#define GEMM_DSMEM (NSTG*STG_BYTES + 1024)

__device__ __forceinline__ void gemm_issue_loads(
    const __half* ga, const __half* gw,
    uint32_t base, int slab, int buf, int t)
{
    int k0 = slab * SLAB;
    uint32_t stA = base + buf * STG_BYTES;
    uint32_t stW = stA + AB_BYTES;
    const __half* gak = ga + k0;
    const __half* gwk = gw + k0;
    #pragma unroll
    for (int j = 0; j < 4; j++) {
        int i = t + j * 256;            // 0..1023
        int row = i >> 3, c = i & 7;
        cp_async16(stA + swz(row * 128 + c * 16), gak + (size_t)row * KTOT + c * 8);
    }
    #pragma unroll
    for (int j = 0; j < 4; j++) {
        int i = t + j * 256;
        int row = i >> 3, c = i & 7;
        cp_async16(stW + swz(row * 128 + c * 16), gwk + (size_t)row * KTOT + c * 8);
    }
    cp_commit();
}

struct GemmFrag { float acc[4][4][4]; };

__device__ __forceinline__ void gemm_mainloop(
    const __half* ga, const __half* gw, uint32_t base, int t, GemmFrag& F)
{
    const int wid = t >> 5, lane = t & 31;
    const int wm = wid >> 2;
    const int wn = wid & 3;
    #pragma unroll
    for (int mi = 0; mi < 4; mi++)
        #pragma unroll
        for (int ni = 0; ni < 4; ni++)
            #pragma unroll
            for (int r = 0; r < 4; r++) F.acc[mi][ni][r] = 0.f;

    #pragma unroll
    for (int s = 0; s < NSTG - 1; s++) gemm_issue_loads(ga, gw, base, s, s, t);

    const int lrow = lane & 15;
    const int lhalf = (lane >> 4) * 16;

    for (int i = 0; i < NSLAB; i++) {
        cp_wait_group<NSTG - 2>();
        __syncthreads();
        if (i + NSTG - 1 < NSLAB)
            gemm_issue_loads(ga, gw, base, i + NSTG - 1, (i + NSTG - 1) % NSTG, t);
        else
            cp_commit();

        uint32_t sA = base + (i % NSTG) * STG_BYTES;
        uint32_t sB = sA + AB_BYTES;

        #pragma unroll
        for (int kk = 0; kk < 4; kk++) {
            uint32_t a[4][4], b[2][4];
            #pragma unroll
            for (int mi = 0; mi < 4; mi++) {
                uint32_t off = (uint32_t)(wm * 64 + mi * 16 + lrow) * 128 + kk * 32 + lhalf;
                ldmatrix_x4(a[mi], sA + swz(off));
            }
            #pragma unroll
            for (int nb = 0; nb < 2; nb++) {
                uint32_t off = (uint32_t)(wn * 32 + nb * 16 + lrow) * 128 + kk * 32 + lhalf;
                ldmatrix_x4(b[nb], sB + swz(off));
            }
            #pragma unroll
            for (int mi = 0; mi < 4; mi++)
                #pragma unroll
                for (int ni = 0; ni < 4; ni++) {
                    int nb = ni >> 1, hi = ni & 1;
                    mma_fp16(F.acc[mi][ni], a[mi], b[nb][hi], b[nb][hi + 2]);
                }
        }
        __syncthreads();
    }
}

// fp32 epilogue (Wo output)
__device__ __forceinline__ void gemm_epilogue_f32(
    GemmFrag& F, const float* bias, float* C, int bm, int cn, int t)
{
    const int wid = t >> 5, lane = t & 31;
    const int wm = wid >> 2, wn = wid & 3;
    const int qrow = lane >> 2;
    const int qcol = (lane & 3) * 2;
    #pragma unroll
    for (int mi = 0; mi < 4; mi++) {
        int row0 = bm + wm * 64 + mi * 16 + qrow;
        #pragma unroll
        for (int ni = 0; ni < 4; ni++) {
            int col = cn + wn * 32 + ni * 8 + qcol;
            float2 bb = *(const float2*)&bias[col];
            *(float2*)&C[(size_t)row0 * E_ + col] =
                make_float2(F.acc[mi][ni][0] + bb.x, F.acc[mi][ni][1] + bb.y);
            *(float2*)&C[(size_t)(row0 + 8) * E_ + col] =
                make_float2(F.acc[mi][ni][2] + bb.x, F.acc[mi][ni][3] + bb.y);
        }
    }
}

// fp16 epilogue (q/k/v outputs)
__device__ __forceinline__ void gemm_epilogue_f16(
    GemmFrag& F, const float* bias, __half* C, int bm, int cn, bool relu, int t)
{
    const int wid = t >> 5, lane = t & 31;
    const int wm = wid >> 2, wn = wid & 3;
    const int qrow = lane >> 2;
    const int qcol = (lane & 3) * 2;
    #pragma unroll
    for (int mi = 0; mi < 4; mi++) {
        int row0 = bm + wm * 64 + mi * 16 + qrow;
        #pragma unroll
        for (int ni = 0; ni < 4; ni++) {
            int col = cn + wn * 32 + ni * 8 + qcol;
            float2 bb = *(const float2*)&bias[col];
            float v0 = F.acc[mi][ni][0] + bb.x;
            float v1 = F.acc[mi][ni][1] + bb.y;
            float v2 = F.acc[mi][ni][2] + bb.x;
            float v3 = F.acc[mi][ni][3] + bb.y;
            if (relu) {
                v0 = fmaxf(v0, 0.f); v1 = fmaxf(v1, 0.f);
                v2 = fmaxf(v2, 0.f); v3 = fmaxf(v3, 0.f);
            }
            __half2 p01 = __floats2half2_rn(v0, v1);
            __half2 p23 = __floats2half2_rn(v2, v3);
            *(__half2*)&C[(size_t)row0 * E_ + col]       = p01;
            *(__half2*)&C[(size_t)(row0 + 8) * E_ + col] = p23;
        }
    }
}

// Merged Q/K/V projection: W2all = [Wq2; Wk2; Wv2] rows 0..3071
__global__ __launch_bounds__(256, 2)
void gemm_qkv(const __half* __restrict__ A2, const __half* __restrict__ W2all,
              const float* __restrict__ bq, const float* __restrict__ bk,
              const float* __restrict__ bv,
              __half* __restrict__ qp, __half* __restrict__ kp, __half* __restrict__ vp)
{
    extern __shared__ char dsm[];
    const int t = threadIdx.x;
    const int bm = blockIdx.y * GBM;
    const int bnG = blockIdx.x * GBN;          // 0..2944
    const int seg = bnG >> 10;                 // 0=q 1=k 2=v
    const int cn = bnG & 1023;

    uint32_t base = (smem_u32(dsm) + 1023u) & ~1023u;
    const __half* ga = A2 + (size_t)bm * KTOT;
    const __half* gw = W2all + (size_t)bnG * KTOT;

    GemmFrag F;
    gemm_mainloop(ga, gw, base, t, F);

    const float* bias = (seg == 0) ? bq : (seg == 1) ? bk : bv;
    __half* C = (seg == 0) ? qp : (seg == 1) ? kp : vp;
    gemm_epilogue_f16(F, bias, C, bm, cn, seg < 2, t);
}

// Single-output GEMM (used for Wo)
__global__ __launch_bounds__(256, 2)
void gemm_mma(const __half* __restrict__ A2, const __half* __restrict__ W2,
              const float* __restrict__ bias, float* __restrict__ C)
{
    extern __shared__ char dsm[];
    const int t = threadIdx.x;
    const int bm = blockIdx.y * GBM;
    const int bn = blockIdx.x * GBN;

    uint32_t base = (smem_u32(dsm) + 1023u) & ~1023u;
    const __half* ga = A2 + (size_t)bm * KTOT;
    const __half* gw = W2 + (size_t)bn * KTOT;

    GemmFrag F;
    gemm_mainloop(ga, gw, base, t, F);
    gemm_epilogue_f32(F, bias, C, bm, bn, t);
}

// ================= kv via HMMA (ldmatrix.trans, zero staging) =================
__global__ __launch_bounds__(256, 2)
void kv_hmma(const __half* __restrict__ k, const __half* __restrict__ v)
{
    __shared__ __align__(16) __half Ksm[2][64 * 64];
    __shared__ __align__(16) __half Vsm[2][64 * 64];
    __shared__ __half2 wsin[KVCH / 2], wcos[KVCH / 2];   // 128 pairs each

    const int t = threadIdx.x;
    const int wid = t >> 5, lane = t & 31;
    const int head = blockIdx.x, chunk = blockIdx.y;
    const int b = head / H_, h = head % H_;

    if (t < KVCH / 2) {
        int l0 = chunk * KVCH + t * 2;
        float s0, c0, s1, c1;
        sincosf((float)M_PI * 0.5f * (float)(l0 + 1) / (float)L_, &s0, &c0);
        sincosf((float)M_PI * 0.5f * (float)(l0 + 2) / (float)L_, &s1, &c1);
        wsin[t] = __floats2half2_rn(s0, s1);
        wcos[t] = __floats2half2_rn(c0, c1);
    }

    const __half* kbase = k + ((size_t)(b * L_ + chunk * KVCH)) * E_ + h * HD_;
    const __half* vbase = v + ((size_t)(b * L_ + chunk * KVCH)) * E_ + h * HD_;

    auto issue = [&](int slab, int buf) {
        uint32_t sK = smem_u32(Ksm[buf]);
        uint32_t sV = smem_u32(Vsm[buf]);
        #pragma unroll
        for (int j = 0; j < 4; j++) {
            int i = t + j * 256;            // 0..1023: first 512 = k, next = v
            int idx = i & 511;
            int row = idx >> 3, c = idx & 7;
            const __half* src = ((i >> 9) ? vbase : kbase)
                              + (size_t)(slab * 64 + row) * E_ + c * 8;
            uint32_t dst = ((i >> 9) ? sV : sK) + swz((uint32_t)row * 128 + c * 16);
            cp_async16(dst, src);
        }
        cp_commit();
    };

    float acc[9][4];
    #pragma unroll
    for (int n8 = 0; n8 < 9; n8++)
        #pragma unroll
        for (int r = 0; r < 4; r++) acc[n8][r] = 0.f;

    issue(0, 0);
    const uint32_t ONES = 0x3C003C00u;
    const int d0 = (wid & 3) * 16;

    #pragma unroll
    for (int slab = 0; slab < KVCH / 64; slab++) {     // 4
        if (slab + 1 < KVCH / 64) {
            issue(slab + 1, (slab + 1) & 1);
            cp_wait_group<1>();
        } else {
            cp_wait_group<0>();
        }
        __syncthreads();
        uint32_t sK = smem_u32(Ksm[slab & 1]);
        uint32_t sV = smem_u32(Vsm[slab & 1]);
        const __half2* wsel = (wid < 4) ? wsin : wcos;
        #pragma unroll
        for (int kk = 0; kk < 4; kk++) {
            uint32_t a[4], bf[4][4];
            ldmatrix_x4_trans(a, trans_addr(sK, kk, d0, lane));
            #pragma unroll
            for (int nb = 0; nb < 4; nb++)
                ldmatrix_x4_trans(bf[nb], trans_addr(sV, kk, nb * 16, lane));
            __half2 w0 = wsel[slab * 32 + kk * 8 + (lane & 3)];
            __half2 w1 = wsel[slab * 32 + kk * 8 + (lane & 3) + 4];
            __half2* ah = (__half2*)a;
            ah[0] = __hmul2(ah[0], w0);
            ah[1] = __hmul2(ah[1], w0);
            ah[2] = __hmul2(ah[2], w1);
            ah[3] = __hmul2(ah[3], w1);
            #pragma unroll
            for (int n8 = 0; n8 < 8; n8++)
                mma_fp16(acc[n8], a, bf[n8 >> 1][n8 & 1], bf[n8 >> 1][(n8 & 1) + 2]);
            mma_fp16(acc[8], a, ONES, ONES);
        }
        __syncthreads();
    }

    // epilogue: partial kv + ksum (fp32, R12-exact)
    const int qr = lane >> 2, qc = (lane & 3) * 2;
    float* kvout = &g_kvp[((size_t)(chunk * BH_ + head)) * 128 * HD_];
    #pragma unroll
    for (int n8 = 0; n8 < 8; n8++) {
        int col = n8 * 8 + qc;
        *(float2*)&kvout[(wid * 16 + qr) * HD_ + col]     = make_float2(acc[n8][0], acc[n8][1]);
        *(float2*)&kvout[(wid * 16 + qr + 8) * HD_ + col] = make_float2(acc[n8][2], acc[n8][3]);
    }
    if ((lane & 3) == 0) {
        g_ksump[(chunk * BH_ + head) * 128 + wid * 16 + qr]     = acc[8][0];
        g_ksump[(chunk * BH_ + head) * 128 + wid * 16 + qr + 8] = acc[8][2];
    }
}

// Reduce fp32 partials; emit transposed fp16 kv with coalesced writes.
// grid (BH_, 8): slice = 16 d' rows (1024 elems). smem transpose buffer.
__global__ __launch_bounds__(256)
void kv_reduce()
{
    __shared__ float buf[16][65];
    const int head = blockIdx.x, slice = blockIdx.y;
    const int t = threadIdx.x;

    // accumulate: coalesced reads over e = d'*64 + m
    #pragma unroll
    for (int j = 0; j < 4; j++) {
        int el = t + j * 256;               // 0..1023 local
        int e = slice * 1024 + el;
        float s = 0.f;
        #pragma unroll
        for (int c = 0; c < NCHUNK; c++)
            s += g_kvp[((size_t)(c * BH_ + head)) * 128 * HD_ + e];
        buf[el >> 6][el & 63] = s;          // [d_local][m]
    }
    __syncthreads();

    // write coalesced: g_kvt[head][slab][m][d&63]; slice covers d' = slice*16..+15
    const int d_base = slice * 16;
    const int slab = d_base >> 6;
    const int dmod = d_base & 63;
    __half* outp = g_kvt + (((size_t)head * 2 + slab) * 64) * 64;
    #pragma unroll
    for (int j = 0; j < 4; j++) {
        int o = t + j * 256;                // 0..1023
        int m = o >> 4, dlo = o & 15;
        outp[m * 64 + dmod + dlo] = __float2half_rn(buf[dlo][m]);
    }

    if (slice == 0 && t < 128) {
        float s = 0.f;
        #pragma unroll
        for (int c = 0; c < NCHUNK; c++)
            s += g_ksump[(c * BH_ + head) * 128 + t];
        g_ksum[head * 128 + t] = s;
    }
}

// ================= attn via HMMA =================
// A = q_ fp16 1-term (2 slabs of k64), B = kvt single-term (2 slabs).
// Passes: (A0,B0)(A1,B1) = sum over d' of q_ * kv.
#define ATT_A_SM 32768            // 2 slabs * 128 rows * 128B
#define ATT_B_SM 16384            // 2 slabs * 64 rows * 128B
#define ATT_DSMEM (ATT_A_SM + ATT_B_SM + 128)

__global__ __launch_bounds__(256, 2)
void attn_hmma(const __half* __restrict__ q)
{
    extern __shared__ char dsm[];
    __shared__ float ss[128], cs[128], zs[128], ks_s[128];

    const int t = threadIdx.x;
    const int wid = t >> 5, lane = t & 31;
    const int ltile = blockIdx.x;           // 0..31
    const int head  = blockIdx.y;           // 0..63
    const int b = head / H_, h = head % H_;

    char* sm = (char*)((((uintptr_t)dsm) + 127) & ~(uintptr_t)127);
    uint32_t sA = smem_u32(sm);
    uint32_t sB = sA + ATT_A_SM;

    if (t < 128) {
        int l = ltile * 128 + t;
        float ang = (float)M_PI * 0.5f * (float)(l + 1) / (float)L_;
        sincosf(ang, &ss[t], &cs[t]);
        ks_s[t] = g_ksum[head * 128 + t];
    }

    {
        const __half* kvt = g_kvt + (size_t)head * 128 * 64;
        #pragma unroll
        for (int j = 0; j < 4; j++) {
            int i = t + j * 256;            // 0..1023 16B chunks
            int row = i >> 3, c = i & 7;    // 128 rows of 64 halves
            cp_async16(sB + swz((uint32_t)row * 128 + c * 16),
                       kvt + row * 64 + c * 8);
        }
        cp_commit();
    }
    __syncthreads();

    {
        const int l_loc = t >> 1;           // 0..127
        const int halfsel = t & 1;
        int lg = ltile * 128 + l_loc;
        const __half* qrow = q + ((size_t)(b * L_ + lg)) * E_ + h * HD_;
        float w = halfsel ? cs[l_loc] : ss[l_loc];
        float zpart = 0.f;
        char* aw = sm + halfsel * 16384;    // slab halfsel
        #pragma unroll 4
        for (int it = 0; it < 32; it++) {
            int dp = halfsel * 64 + 2 * it;
            float2 qq = __half22float2(*(const __half2*)&qrow[dp & 63]);
            float f0 = w * qq.x, f1 = w * qq.y;
            zpart += f0 * ks_s[dp] + f1 * ks_s[dp + 1];
            __half2 Hp = __floats2half2_rn(f0, f1);
            uint32_t off = swz((uint32_t)l_loc * 128 + (dp & 63) * 2);
            *(uint32_t*)(aw + off) = *(uint32_t*)&Hp;
        }
        zpart += __shfl_xor_sync(0xffffffffu, zpart, 1);
        if (!halfsel) zs[l_loc] = 1.f / fmaxf(zpart, EPS_);
    }

    cp_wait_group<0>();
    __syncthreads();

    const int wm = wid & 1;
    const int wn = wid >> 1;
    const int lrow = lane & 15;
    const int lhalf = (lane >> 4) * 16;

    float acc[4][2][4];
    #pragma unroll
    for (int mi = 0; mi < 4; mi++)
        #pragma unroll
        for (int hi = 0; hi < 2; hi++)
            #pragma unroll
            for (int r = 0; r < 4; r++) acc[mi][hi][r] = 0.f;

    #pragma unroll
    for (int p = 0; p < 2; p++) {
        uint32_t a_s = sA + p * 16384;
        uint32_t b_s = sB + p * 8192;
        #pragma unroll
        for (int kk = 0; kk < 4; kk++) {
            uint32_t a[4][4], bfr[4];
            #pragma unroll
            for (int mi = 0; mi < 4; mi++) {
                uint32_t off = (uint32_t)(wm * 64 + mi * 16 + lrow) * 128 + kk * 32 + lhalf;
                ldmatrix_x4(a[mi], a_s + swz(off));
            }
            {
                uint32_t off = (uint32_t)(wn * 16 + lrow) * 128 + kk * 32 + lhalf;
                ldmatrix_x4(bfr, b_s + swz(off));
            }
            #pragma unroll
            for (int mi = 0; mi < 4; mi++)
                #pragma unroll
                for (int hi = 0; hi < 2; hi++)
                    mma_fp16(acc[mi][hi], a[mi], bfr[hi], bfr[hi + 2]);
        }
    }

    const int qr = lane >> 2;
    const int qc = (lane & 3) * 2;
    #pragma unroll
    for (int mi = 0; mi < 4; mi++) {
        #pragma unroll
        for (int hi = 0; hi < 2; hi++) {
            #pragma unroll
            for (int r = 0; r < 2; r++) {
                int lloc = wm * 64 + mi * 16 + qr + r * 8;
                int n = wn * 16 + hi * 8 + qc;
                float z = zs[lloc];
                __half2 Hp = __floats2half2_rn(acc[mi][hi][r * 2 + 0] * z,
                                               acc[mi][hi][r * 2 + 1] * z);
                __half* ob = g_attn2 + ((size_t)(b * L_ + ltile * 128 + lloc)) * KTOT
                           + h * HD_ + n;
                *(uint32_t*)(ob) = *(uint32_t*)&Hp;
            }
        }
    }
}

// ================= launcher =================
extern "C" void kernel_launch(void* const* d_in, const int* in_sizes, int n_in,
                              void* d_out, int out_size)
{
    const float* x  = (const float*)d_in[0];
    const float* Wq = (const float*)d_in[1];
    const float* bq = (const float*)d_in[2];
    const float* Wk = (const float*)d_in[3];
    const float* bk = (const float*)d_in[4];
    const float* Wv = (const float*)d_in[5];
    const float* bv = (const float*)d_in[6];
    const float* Wo = (const float*)d_in[7];
    const float* bo = (const float*)d_in[8];
    float* out = (float*)d_out;

    __half *x2, *attn2, *w2, *qh, *kh, *vh;
    cudaGetSymbolAddress((void**)&x2,    g_x2);
    cudaGetSymbolAddress((void**)&attn2, g_attn2);
    cudaGetSymbolAddress((void**)&w2,    g_w2);
    cudaGetSymbolAddress((void**)&qh,    g_qh);
    cudaGetSymbolAddress((void**)&kh,    g_kh);
    cudaGetSymbolAddress((void**)&vh,    g_vh);
    __half* w2o = w2 + (size_t)3 * E_ * KTOT;

    cudaFuncSetAttribute(gemm_mma,  cudaFuncAttributeMaxDynamicSharedMemorySize, GEMM_DSMEM);
    cudaFuncSetAttribute(gemm_qkv,  cudaFuncAttributeMaxDynamicSharedMemorySize, GEMM_DSMEM);
    cudaFuncSetAttribute(attn_hmma, cudaFuncAttributeMaxDynamicSharedMemorySize, ATT_DSMEM);

    // one merged conversion launch: x + 4 weights
    convert_all<<<16384 + 4096, 256>>>(x, Wq, Wk, Wv, Wo, x2, w2);

    // merged QKV projection (fp16 outputs)
    gemm_qkv<<<dim3(3 * E_ / GBN, M_ / GBM), 256, GEMM_DSMEM>>>(
        x2, w2, bq, bk, bv, qh, kh, vh);

    kv_hmma<<<dim3(BH_, NCHUNK), 256>>>(kh, vh);
    kv_reduce<<<dim3(BH_, 8), 256>>>();
    attn_hmma<<<dim3(32, BH_), 256, ATT_DSMEM>>>(qh);

    gemm_mma<<<dim3(E_ / GBN, M_ / GBM), 256, GEMM_DSMEM>>>(attn2, w2o, bo, out);
}

// round 15
// speedup vs baseline: 1.5102x; 1.0035x over previous
#include <cuda_runtime.h>
#include <cuda_fp16.h>
#include <math.h>
#include <stdint.h>

#define B_   4
#define L_   4096
#define E_   1024
#define H_   16
#define HD_  64
#define M_   (B_*L_)    // 16384 rows
#define BH_  (B_*H_)    // 64 heads
#define EPS_ 1e-4f
#define KTOT 1024       // plain 1-term fp16
#define NCHUNK 16       // kv l-chunks
#define KVCH (L_/NCHUNK) // 256

// ---------------- scratch (no allocations allowed) ----------------
__device__ __half g_x2[(size_t)M_*KTOT];
__device__ __half g_attn2[(size_t)M_*KTOT];
__device__ __half g_w2[4][(size_t)E_*KTOT];
__device__ __half g_qh[(size_t)M_*E_];
__device__ __half g_kh[(size_t)M_*E_];
__device__ __half g_vh[(size_t)M_*E_];
__device__ __half g_kvph[(size_t)NCHUNK*BH_*128*HD_];   // fp16 partials [chunk][head][d'(128)][m(64)]
__device__ float g_ksump[NCHUNK*BH_*128];
__device__ float g_ksum[BH_*128];
__device__ __half g_kvt[(size_t)BH_*128*64];  // [head][slab(2)][m(64)][d(64)] fp16

// ================= PTX helpers (sm_80-generic only!) =================
__device__ __forceinline__ uint32_t smem_u32(const void* p) {
    uint32_t a;
    asm("{ .reg .u64 t; cvta.to.shared.u64 t, %1; cvt.u32.u64 %0, t; }" : "=r"(a) : "l"(p));
    return a;
}
__device__ __forceinline__ void cp_async16(uint32_t saddr, const void* gaddr) {
    asm volatile("cp.async.cg.shared.global [%0], [%1], 16;" :: "r"(saddr), "l"(gaddr) : "memory");
}
__device__ __forceinline__ void cp_commit() {
    asm volatile("cp.async.commit_group;" ::: "memory");
}
template<int N> __device__ __forceinline__ void cp_wait_group() {
    asm volatile("cp.async.wait_group %0;" :: "n"(N) : "memory");
}
__device__ __forceinline__ void ldmatrix_x4(uint32_t* r, uint32_t addr) {
    asm volatile("ldmatrix.sync.aligned.m8n8.x4.shared.b16 {%0,%1,%2,%3}, [%4];"
        : "=r"(r[0]), "=r"(r[1]), "=r"(r[2]), "=r"(r[3]) : "r"(addr));
}
__device__ __forceinline__ void ldmatrix_x4_trans(uint32_t* r, uint32_t addr) {
    asm volatile("ldmatrix.sync.aligned.m8n8.x4.trans.shared.b16 {%0,%1,%2,%3}, [%4];"
        : "=r"(r[0]), "=r"(r[1]), "=r"(r[2]), "=r"(r[3]) : "r"(addr));
}
__device__ __forceinline__ void mma_fp16(float* c, const uint32_t* a, uint32_t b0, uint32_t b1) {
    asm volatile("mma.sync.aligned.m16n8k16.row.col.f32.f16.f16.f32 "
        "{%0,%1,%2,%3}, {%4,%5,%6,%7}, {%8,%9}, {%0,%1,%2,%3};"
        : "+f"(c[0]), "+f"(c[1]), "+f"(c[2]), "+f"(c[3])
        : "r"(a[0]), "r"(a[1]), "r"(a[2]), "r"(a[3]), "r"(b0), "r"(b1));
}
__device__ __forceinline__ uint32_t swz(uint32_t off) { return off ^ ((off >> 3) & 0x70); }

// address for ldmatrix.x4.trans over a [row][64 halves] swizzled tile
__device__ __forceinline__ uint32_t trans_addr(uint32_t base, int kk, int colhalf, int lane) {
    int mat = lane >> 3, r = lane & 7;
    int lrow = kk * 16 + ((mat & 2) << 2) + r;
    int cb = colhalf * 2 + ((mat & 1) << 4);
    return base + swz((uint32_t)lrow * 128 + cb);
}

// ================= merged fp32 -> fp16 convert (x + 4 weights) =================
// blocks [0,16384): x ; [16384, 16384+4*1024): weights
__global__ void convert_all(const float* __restrict__ x,
                            const float* __restrict__ w0, const float* __restrict__ w1,
                            const float* __restrict__ w2s, const float* __restrict__ w3,
                            __half* __restrict__ x2, __half* __restrict__ wout)
{
    int bid = blockIdx.x;
    const float* in;
    __half* out;
    int idx;
    if (bid < 16384) {
        in = x; out = g_x2;   // == x2
        idx = bid * 256 + threadIdx.x;
    } else {
        int wb = bid - 16384;
        int seg = wb >> 10;
        in = (seg == 0) ? w0 : (seg == 1) ? w1 : (seg == 2) ? w2s : w3;
        out = wout + (size_t)seg * E_ * KTOT;
        idx = (wb & 1023) * 256 + threadIdx.x;
    }
    float4 v = *(const float4*)&in[(size_t)idx * 4];
    union { __half b[4]; uint2 u; } Hh;
    Hh.b[0] = __float2half_rn(v.x);
    Hh.b[1] = __float2half_rn(v.y);
    Hh.b[2] = __float2half_rn(v.z);
    Hh.b[3] = __float2half_rn(v.w);
    *(uint2*)&out[(size_t)idx * 4] = Hh.u;
}

// ================= HMMA GEMM =================
// Tile 128x128x64, 8 warps, warp tile 64x32, mma.sync m16n8k16.
#define GBM 128
#define GBN 128
#define SLAB 64                 // fp16 K per slab = 128 bytes per row
#define NSLAB (KTOT/SLAB)       // 16
#define NSTG 3
#define AB_BYTES (GBM*128)      // 16384 (A tile == B tile size)
#define STG_BYTES (2*AB_BYTES)  // 32768
#define GEMM_DSMEM (NSTG*STG_BYTES + 1024)

__device__ __forceinline__ void gemm_issue_loads(
    const __half* ga, const __half* gw,
    uint32_t base, int slab, int buf, int t)
{
    int k0 = slab * SLAB;
    uint32_t stA = base + buf * STG_BYTES;
    uint32_t stW = stA + AB_BYTES;
    const __half* gak = ga + k0;
    const __half* gwk = gw + k0;
    #pragma unroll
    for (int j = 0; j < 4; j++) {
        int i = t + j * 256;            // 0..1023
        int row = i >> 3, c = i & 7;
        cp_async16(stA + swz(row * 128 + c * 16), gak + (size_t)row * KTOT + c * 8);
    }
    #pragma unroll
    for (int j = 0; j < 4; j++) {
        int i = t + j * 256;
        int row = i >> 3, c = i & 7;
        cp_async16(stW + swz(row * 128 + c * 16), gwk + (size_t)row * KTOT + c * 8);
    }
    cp_commit();
}

struct GemmFrag { float acc[4][4][4]; };

__device__ __forceinline__ void gemm_mainloop(
    const __half* ga, const __half* gw, uint32_t base, int t, GemmFrag& F)
{
    const int wid = t >> 5, lane = t & 31;
    const int wm = wid >> 2;
    const int wn = wid & 3;
    #pragma unroll
    for (int mi = 0; mi < 4; mi++)
        #pragma unroll
        for (int ni = 0; ni < 4; ni++)
            #pragma unroll
            for (int r = 0; r < 4; r++) F.acc[mi][ni][r] = 0.f;

    #pragma unroll
    for (int s = 0; s < NSTG - 1; s++) gemm_issue_loads(ga, gw, base, s, s, t);

    const int lrow = lane & 15;
    const int lhalf = (lane >> 4) * 16;

    for (int i = 0; i < NSLAB; i++) {
        cp_wait_group<NSTG - 2>();
        __syncthreads();
        if (i + NSTG - 1 < NSLAB)
            gemm_issue_loads(ga, gw, base, i + NSTG - 1, (i + NSTG - 1) % NSTG, t);
        else
            cp_commit();

        uint32_t sA = base + (i % NSTG) * STG_BYTES;
        uint32_t sB = sA + AB_BYTES;

        #pragma unroll
        for (int kk = 0; kk < 4; kk++) {
            uint32_t a[4][4], b[2][4];
            #pragma unroll
            for (int mi = 0; mi < 4; mi++) {
                uint32_t off = (uint32_t)(wm * 64 + mi * 16 + lrow) * 128 + kk * 32 + lhalf;
                ldmatrix_x4(a[mi], sA + swz(off));
            }
            #pragma unroll
            for (int nb = 0; nb < 2; nb++) {
                uint32_t off = (uint32_t)(wn * 32 + nb * 16 + lrow) * 128 + kk * 32 + lhalf;
                ldmatrix_x4(b[nb], sB + swz(off));
            }
            #pragma unroll
            for (int mi = 0; mi < 4; mi++)
                #pragma unroll
                for (int ni = 0; ni < 4; ni++) {
                    int nb = ni >> 1, hi = ni & 1;
                    mma_fp16(F.acc[mi][ni], a[mi], b[nb][hi], b[nb][hi + 2]);
                }
        }
        __syncthreads();
    }
}

// fp32 epilogue (Wo output)
__device__ __forceinline__ void gemm_epilogue_f32(
    GemmFrag& F, const float* bias, float* C, int bm, int cn, int t)
{
    const int wid = t >> 5, lane = t & 31;
    const int wm = wid >> 2, wn = wid & 3;
    const int qrow = lane >> 2;
    const int qcol = (lane & 3) * 2;
    #pragma unroll
    for (int mi = 0; mi < 4; mi++) {
        int row0 = bm + wm * 64 + mi * 16 + qrow;
        #pragma unroll
        for (int ni = 0; ni < 4; ni++) {
            int col = cn + wn * 32 + ni * 8 + qcol;
            float2 bb = *(const float2*)&bias[col];
            *(float2*)&C[(size_t)row0 * E_ + col] =
                make_float2(F.acc[mi][ni][0] + bb.x, F.acc[mi][ni][1] + bb.y);
            *(float2*)&C[(size_t)(row0 + 8) * E_ + col] =
                make_float2(F.acc[mi][ni][2] + bb.x, F.acc[mi][ni][3] + bb.y);
        }
    }
}

// fp16 epilogue (q/k/v outputs)
__device__ __forceinline__ void gemm_epilogue_f16(
    GemmFrag& F, const float* bias, __half* C, int bm, int cn, bool relu, int t)
{
    const int wid = t >> 5, lane = t & 31;
    const int wm = wid >> 2, wn = wid & 3;
    const int qrow = lane >> 2;
    const int qcol = (lane & 3) * 2;
    #pragma unroll
    for (int mi = 0; mi < 4; mi++) {
        int row0 = bm + wm * 64 + mi * 16 + qrow;
        #pragma unroll
        for (int ni = 0; ni < 4; ni++) {
            int col = cn + wn * 32 + ni * 8 + qcol;
            float2 bb = *(const float2*)&bias[col];
            float v0 = F.acc[mi][ni][0] + bb.x;
            float v1 = F.acc[mi][ni][1] + bb.y;
            float v2 = F.acc[mi][ni][2] + bb.x;
            float v3 = F.acc[mi][ni][3] + bb.y;
            if (relu) {
                v0 = fmaxf(v0, 0.f); v1 = fmaxf(v1, 0.f);
                v2 = fmaxf(v2, 0.f); v3 = fmaxf(v3, 0.f);
            }
            __half2 p01 = __floats2half2_rn(v0, v1);
            __half2 p23 = __floats2half2_rn(v2, v3);
            *(__half2*)&C[(size_t)row0 * E_ + col]       = p01;
            *(__half2*)&C[(size_t)(row0 + 8) * E_ + col] = p23;
        }
    }
}

// Merged Q/K/V projection: W2all = [Wq2; Wk2; Wv2] rows 0..3071
__global__ __launch_bounds__(256, 2)
void gemm_qkv(const __half* __restrict__ A2, const __half* __restrict__ W2all,
              const float* __restrict__ bq, const float* __restrict__ bk,
              const float* __restrict__ bv,
              __half* __restrict__ qp, __half* __restrict__ kp, __half* __restrict__ vp)
{
    extern __shared__ char dsm[];
    const int t = threadIdx.x;
    const int bm = blockIdx.y * GBM;
    const int bnG = blockIdx.x * GBN;          // 0..2944
    const int seg = bnG >> 10;                 // 0=q 1=k 2=v
    const int cn = bnG & 1023;

    uint32_t base = (smem_u32(dsm) + 1023u) & ~1023u;
    const __half* ga = A2 + (size_t)bm * KTOT;
    const __half* gw = W2all + (size_t)bnG * KTOT;

    GemmFrag F;
    gemm_mainloop(ga, gw, base, t, F);

    const float* bias = (seg == 0) ? bq : (seg == 1) ? bk : bv;
    __half* C = (seg == 0) ? qp : (seg == 1) ? kp : vp;
    gemm_epilogue_f16(F, bias, C, bm, cn, seg < 2, t);
}

// Single-output GEMM (used for Wo)
__global__ __launch_bounds__(256, 2)
void gemm_mma(const __half* __restrict__ A2, const __half* __restrict__ W2,
              const float* __restrict__ bias, float* __restrict__ C)
{
    extern __shared__ char dsm[];
    const int t = threadIdx.x;
    const int bm = blockIdx.y * GBM;
    const int bn = blockIdx.x * GBN;

    uint32_t base = (smem_u32(dsm) + 1023u) & ~1023u;
    const __half* ga = A2 + (size_t)bm * KTOT;
    const __half* gw = W2 + (size_t)bn * KTOT;

    GemmFrag F;
    gemm_mainloop(ga, gw, base, t, F);
    gemm_epilogue_f32(F, bias, C, bm, bn, t);
}

// ================= kv via HMMA (ldmatrix.trans, zero staging) =================
__global__ __launch_bounds__(256, 2)
void kv_hmma(const __half* __restrict__ k, const __half* __restrict__ v)
{
    __shared__ __align__(16) __half Ksm[2][64 * 64];
    __shared__ __align__(16) __half Vsm[2][64 * 64];
    __shared__ __half2 wsin[KVCH / 2], wcos[KVCH / 2];   // 128 pairs each

    const int t = threadIdx.x;
    const int wid = t >> 5, lane = t & 31;
    const int head = blockIdx.x, chunk = blockIdx.y;
    const int b = head / H_, h = head % H_;

    if (t < KVCH / 2) {
        int l0 = chunk * KVCH + t * 2;
        float s0, c0, s1, c1;
        sincosf((float)M_PI * 0.5f * (float)(l0 + 1) / (float)L_, &s0, &c0);
        sincosf((float)M_PI * 0.5f * (float)(l0 + 2) / (float)L_, &s1, &c1);
        wsin[t] = __floats2half2_rn(s0, s1);
        wcos[t] = __floats2half2_rn(c0, c1);
    }

    const __half* kbase = k + ((size_t)(b * L_ + chunk * KVCH)) * E_ + h * HD_;
    const __half* vbase = v + ((size_t)(b * L_ + chunk * KVCH)) * E_ + h * HD_;

    auto issue = [&](int slab, int buf) {
        uint32_t sK = smem_u32(Ksm[buf]);
        uint32_t sV = smem_u32(Vsm[buf]);
        #pragma unroll
        for (int j = 0; j < 4; j++) {
            int i = t + j * 256;            // 0..1023: first 512 = k, next = v
            int idx = i & 511;
            int row = idx >> 3, c = idx & 7;
            const __half* src = ((i >> 9) ? vbase : kbase)
                              + (size_t)(slab * 64 + row) * E_ + c * 8;
            uint32_t dst = ((i >> 9) ? sV : sK) + swz((uint32_t)row * 128 + c * 16);
            cp_async16(dst, src);
        }
        cp_commit();
    };

    float acc[9][4];
    #pragma unroll
    for (int n8 = 0; n8 < 9; n8++)
        #pragma unroll
        for (int r = 0; r < 4; r++) acc[n8][r] = 0.f;

    issue(0, 0);
    const uint32_t ONES = 0x3C003C00u;
    const int d0 = (wid & 3) * 16;

    #pragma unroll
    for (int slab = 0; slab < KVCH / 64; slab++) {     // 4
        if (slab + 1 < KVCH / 64) {
            issue(slab + 1, (slab + 1) & 1);
            cp_wait_group<1>();
        } else {
            cp_wait_group<0>();
        }
        __syncthreads();
        uint32_t sK = smem_u32(Ksm[slab & 1]);
        uint32_t sV = smem_u32(Vsm[slab & 1]);
        const __half2* wsel = (wid < 4) ? wsin : wcos;
        #pragma unroll
        for (int kk = 0; kk < 4; kk++) {
            uint32_t a[4], bf[4][4];
            ldmatrix_x4_trans(a, trans_addr(sK, kk, d0, lane));
            #pragma unroll
            for (int nb = 0; nb < 4; nb++)
                ldmatrix_x4_trans(bf[nb], trans_addr(sV, kk, nb * 16, lane));
            __half2 w0 = wsel[slab * 32 + kk * 8 + (lane & 3)];
            __half2 w1 = wsel[slab * 32 + kk * 8 + (lane & 3) + 4];
            __half2* ah = (__half2*)a;
            ah[0] = __hmul2(ah[0], w0);
            ah[1] = __hmul2(ah[1], w0);
            ah[2] = __hmul2(ah[2], w1);
            ah[3] = __hmul2(ah[3], w1);
            #pragma unroll
            for (int n8 = 0; n8 < 8; n8++)
                mma_fp16(acc[n8], a, bf[n8 >> 1][n8 & 1], bf[n8 >> 1][(n8 & 1) + 2]);
            mma_fp16(acc[8], a, ONES, ONES);
        }
        __syncthreads();
    }

    // epilogue: fp16 partial kv + fp32 ksum partial
    const int qr = lane >> 2, qc = (lane & 3) * 2;
    __half* kvout = g_kvph + ((size_t)(chunk * BH_ + head)) * 128 * HD_;
    #pragma unroll
    for (int n8 = 0; n8 < 8; n8++) {
        int col = n8 * 8 + qc;
        __half2 p01 = __floats2half2_rn(acc[n8][0], acc[n8][1]);
        __half2 p23 = __floats2half2_rn(acc[n8][2], acc[n8][3]);
        *(__half2*)&kvout[(wid * 16 + qr) * HD_ + col]     = p01;
        *(__half2*)&kvout[(wid * 16 + qr + 8) * HD_ + col] = p23;
    }
    if ((lane & 3) == 0) {
        g_ksump[(chunk * BH_ + head) * 128 + wid * 16 + qr]     = acc[8][0];
        g_ksump[(chunk * BH_ + head) * 128 + wid * 16 + qr + 8] = acc[8][2];
    }
}

// Reduce fp16 partials; emit transposed fp16 kv, fully coalesced both sides.
// grid (BH_, 2): one block per (head, slab of 64 d'). smem [64][65] transpose.
__global__ __launch_bounds__(256)
void kv_reduce()
{
    __shared__ float buf[64][65];
    const int head = blockIdx.x, slab = blockIdx.y;
    const int t = threadIdx.x;

    // accumulate: 4096 elems = 2048 half2 pairs, coalesced reads
    #pragma unroll
    for (int j = 0; j < 8; j++) {
        int p = t + j * 256;                // 0..2047
        int el = p * 2;                     // 0..4094
        int e = slab * 4096 + el;
        float2 s = make_float2(0.f, 0.f);
        #pragma unroll
        for (int c = 0; c < NCHUNK; c++) {
            __half2 hv = *(const __half2*)&g_kvph[((size_t)(c * BH_ + head)) * 128 * HD_ + e];
            float2 f = __half22float2(hv);
            s.x += f.x; s.y += f.y;
        }
        int dl = el >> 6, m = el & 63;      // local d' row, m pair start
        buf[dl][m]     = s.x;
        buf[dl][m + 1] = s.y;
    }
    __syncthreads();

    // write full 128B rows: g_kvt[head][slab][m][d 0..63]
    __half* outp = g_kvt + (((size_t)head * 2 + slab) * 64) * 64;
    #pragma unroll
    for (int j = 0; j < 8; j++) {
        int o = t + j * 256;                // 0..2047 half2 slots
        int m = o >> 5, d2 = o & 31;
        __half2 hv = __floats2half2_rn(buf[d2 * 2][m], buf[d2 * 2 + 1][m]);
        *(__half2*)&outp[m * 64 + d2 * 2] = hv;
    }

    if (slab == 0 && t < 128) {
        float s = 0.f;
        #pragma unroll
        for (int c = 0; c < NCHUNK; c++)
            s += g_ksump[(c * BH_ + head) * 128 + t];
        g_ksum[head * 128 + t] = s;
    }
}

// ================= attn via HMMA =================
// A = q_ fp16 1-term (2 slabs of k64), B = kvt single-term (2 slabs).
// Passes: (A0,B0)(A1,B1) = sum over d' of q_ * kv.
#define ATT_A_SM 32768            // 2 slabs * 128 rows * 128B
#define ATT_B_SM 16384            // 2 slabs * 64 rows * 128B
#define ATT_DSMEM (ATT_A_SM + ATT_B_SM + 128)

__global__ __launch_bounds__(256, 2)
void attn_hmma(const __half* __restrict__ q)
{
    extern __shared__ char dsm[];
    __shared__ float ss[128], cs[128], zs[128], ks_s[128];

    const int t = threadIdx.x;
    const int wid = t >> 5, lane = t & 31;
    const int ltile = blockIdx.x;           // 0..31
    const int head  = blockIdx.y;           // 0..63
    const int b = head / H_, h = head % H_;

    char* sm = (char*)((((uintptr_t)dsm) + 127) & ~(uintptr_t)127);
    uint32_t sA = smem_u32(sm);
    uint32_t sB = sA + ATT_A_SM;

    if (t < 128) {
        int l = ltile * 128 + t;
        float ang = (float)M_PI * 0.5f * (float)(l + 1) / (float)L_;
        sincosf(ang, &ss[t], &cs[t]);
        ks_s[t] = g_ksum[head * 128 + t];
    }

    {
        const __half* kvt = g_kvt + (size_t)head * 128 * 64;
        #pragma unroll
        for (int j = 0; j < 4; j++) {
            int i = t + j * 256;            // 0..1023 16B chunks
            int row = i >> 3, c = i & 7;    // 128 rows of 64 halves
            cp_async16(sB + swz((uint32_t)row * 128 + c * 16),
                       kvt + row * 64 + c * 8);
        }
        cp_commit();
    }
    __syncthreads();

    {
        const int l_loc = t >> 1;           // 0..127
        const int halfsel = t & 1;
        int lg = ltile * 128 + l_loc;
        const __half* qrow = q + ((size_t)(b * L_ + lg)) * E_ + h * HD_;
        float w = halfsel ? cs[l_loc] : ss[l_loc];
        float zpart = 0.f;
        char* aw = sm + halfsel * 16384;    // slab halfsel
        #pragma unroll 4
        for (int it = 0; it < 32; it++) {
            int dp = halfsel * 64 + 2 * it;
            float2 qq = __half22float2(*(const __half2*)&qrow[dp & 63]);
            float f0 = w * qq.x, f1 = w * qq.y;
            zpart += f0 * ks_s[dp] + f1 * ks_s[dp + 1];
            __half2 Hp = __floats2half2_rn(f0, f1);
            uint32_t off = swz((uint32_t)l_loc * 128 + (dp & 63) * 2);
            *(uint32_t*)(aw + off) = *(uint32_t*)&Hp;
        }
        zpart += __shfl_xor_sync(0xffffffffu, zpart, 1);
        if (!halfsel) zs[l_loc] = 1.f / fmaxf(zpart, EPS_);
    }

    cp_wait_group<0>();
    __syncthreads();

    const int wm = wid & 1;
    const int wn = wid >> 1;
    const int lrow = lane & 15;
    const int lhalf = (lane >> 4) * 16;

    float acc[4][2][4];
    #pragma unroll
    for (int mi = 0; mi < 4; mi++)
        #pragma unroll
        for (int hi = 0; hi < 2; hi++)
            #pragma unroll
            for (int r = 0; r < 4; r++) acc[mi][hi][r] = 0.f;

    #pragma unroll
    for (int p = 0; p < 2; p++) {
        uint32_t a_s = sA + p * 16384;
        uint32_t b_s = sB + p * 8192;
        #pragma unroll
        for (int kk = 0; kk < 4; kk++) {
            uint32_t a[4][4], bfr[4];
            #pragma unroll
            for (int mi = 0; mi < 4; mi++) {
                uint32_t off = (uint32_t)(wm * 64 + mi * 16 + lrow) * 128 + kk * 32 + lhalf;
                ldmatrix_x4(a[mi], a_s + swz(off));
            }
            {
                uint32_t off = (uint32_t)(wn * 16 + lrow) * 128 + kk * 32 + lhalf;
                ldmatrix_x4(bfr, b_s + swz(off));
            }
            #pragma unroll
            for (int mi = 0; mi < 4; mi++)
                #pragma unroll
                for (int hi = 0; hi < 2; hi++)
                    mma_fp16(acc[mi][hi], a[mi], bfr[hi], bfr[hi + 2]);
        }
    }

    const int qr = lane >> 2;
    const int qc = (lane & 3) * 2;
    #pragma unroll
    for (int mi = 0; mi < 4; mi++) {
        #pragma unroll
        for (int hi = 0; hi < 2; hi++) {
            #pragma unroll
            for (int r = 0; r < 2; r++) {
                int lloc = wm * 64 + mi * 16 + qr + r * 8;
                int n = wn * 16 + hi * 8 + qc;
                float z = zs[lloc];
                __half2 Hp = __floats2half2_rn(acc[mi][hi][r * 2 + 0] * z,
                                               acc[mi][hi][r * 2 + 1] * z);
                __half* ob = g_attn2 + ((size_t)(b * L_ + ltile * 128 + lloc)) * KTOT
                           + h * HD_ + n;
                *(uint32_t*)(ob) = *(uint32_t*)&Hp;
            }
        }
    }
}

// ================= launcher =================
extern "C" void kernel_launch(void* const* d_in, const int* in_sizes, int n_in,
                              void* d_out, int out_size)
{
    const float* x  = (const float*)d_in[0];
    const float* Wq = (const float*)d_in[1];
    const float* bq = (const float*)d_in[2];
    const float* Wk = (const float*)d_in[3];
    const float* bk = (const float*)d_in[4];
    const float* Wv = (const float*)d_in[5];
    const float* bv = (const float*)d_in[6];
    const float* Wo = (const float*)d_in[7];
    const float* bo = (const float*)d_in[8];
    float* out = (float*)d_out;

    __half *x2, *attn2, *w2, *qh, *kh, *vh;
    cudaGetSymbolAddress((void**)&x2,    g_x2);
    cudaGetSymbolAddress((void**)&attn2, g_attn2);
    cudaGetSymbolAddress((void**)&w2,    g_w2);
    cudaGetSymbolAddress((void**)&qh,    g_qh);
    cudaGetSymbolAddress((void**)&kh,    g_kh);
    cudaGetSymbolAddress((void**)&vh,    g_vh);
    __half* w2o = w2 + (size_t)3 * E_ * KTOT;

    cudaFuncSetAttribute(gemm_mma,  cudaFuncAttributeMaxDynamicSharedMemorySize, GEMM_DSMEM);
    cudaFuncSetAttribute(gemm_qkv,  cudaFuncAttributeMaxDynamicSharedMemorySize, GEMM_DSMEM);
    cudaFuncSetAttribute(attn_hmma, cudaFuncAttributeMaxDynamicSharedMemorySize, ATT_DSMEM);

    // one merged conversion launch: x + 4 weights
    convert_all<<<16384 + 4096, 256>>>(x, Wq, Wk, Wv, Wo, x2, w2);

    // merged QKV projection (fp16 outputs)
    gemm_qkv<<<dim3(3 * E_ / GBN, M_ / GBM), 256, GEMM_DSMEM>>>(
        x2, w2, bq, bk, bv, qh, kh, vh);

    kv_hmma<<<dim3(BH_, NCHUNK), 256>>>(kh, vh);
    kv_reduce<<<dim3(BH_, 2), 256>>>();
    attn_hmma<<<dim3(32, BH_), 256, ATT_DSMEM>>>(qh);

    gemm_mma<<<dim3(E_ / GBN, M_ / GBM), 256, GEMM_DSMEM>>>(attn2, w2o, bo, out);
}

// round 16
// speedup vs baseline: 1.5226x; 1.0082x over previous
#include <cuda_runtime.h>
#include <cuda_fp16.h>
#include <math.h>
#include <stdint.h>

#define B_   4
#define L_   4096
#define E_   1024
#define H_   16
#define HD_  64
#define M_   (B_*L_)    // 16384 rows
#define BH_  (B_*H_)    // 64 heads
#define EPS_ 1e-4f
#define KTOT 1024       // plain 1-term fp16
#define NCHUNK 16       // kv l-chunks
#define KVCH (L_/NCHUNK) // 256

// ---------------- scratch (no allocations allowed) ----------------
__device__ __half g_x2[(size_t)M_*KTOT];
__device__ __half g_attn2[(size_t)M_*KTOT];
__device__ __half g_w2[4][(size_t)E_*KTOT];
__device__ __half g_qh[(size_t)M_*E_];
__device__ __half g_kh[(size_t)M_*E_];
__device__ __half g_vh[(size_t)M_*E_];
__device__ __half g_kvph[(size_t)NCHUNK*BH_*128*HD_];   // fp16 partials [chunk][head][d'(128)][m(64)]
__device__ float g_ksump[NCHUNK*BH_*128];
__device__ float g_ksum[BH_*128];
__device__ __half g_kvt[(size_t)BH_*128*64];  // [head][slab(2)][m(64)][d(64)] fp16

// ================= PTX helpers (sm_80-generic only!) =================
__device__ __forceinline__ uint32_t smem_u32(const void* p) {
    uint32_t a;
    asm("{ .reg .u64 t; cvta.to.shared.u64 t, %1; cvt.u32.u64 %0, t; }" : "=r"(a) : "l"(p));
    return a;
}
__device__ __forceinline__ void cp_async16(uint32_t saddr, const void* gaddr) {
    asm volatile("cp.async.cg.shared.global [%0], [%1], 16;" :: "r"(saddr), "l"(gaddr) : "memory");
}
__device__ __forceinline__ void cp_commit() {
    asm volatile("cp.async.commit_group;" ::: "memory");
}
template<int N> __device__ __forceinline__ void cp_wait_group() {
    asm volatile("cp.async.wait_group %0;" :: "n"(N) : "memory");
}
__device__ __forceinline__ void ldmatrix_x4(uint32_t* r, uint32_t addr) {
    asm volatile("ldmatrix.sync.aligned.m8n8.x4.shared.b16 {%0,%1,%2,%3}, [%4];"
        : "=r"(r[0]), "=r"(r[1]), "=r"(r[2]), "=r"(r[3]) : "r"(addr));
}
__device__ __forceinline__ void ldmatrix_x4_trans(uint32_t* r, uint32_t addr) {
    asm volatile("ldmatrix.sync.aligned.m8n8.x4.trans.shared.b16 {%0,%1,%2,%3}, [%4];"
        : "=r"(r[0]), "=r"(r[1]), "=r"(r[2]), "=r"(r[3]) : "r"(addr));
}
__device__ __forceinline__ void mma_fp16(float* c, const uint32_t* a, uint32_t b0, uint32_t b1) {
    asm volatile("mma.sync.aligned.m16n8k16.row.col.f32.f16.f16.f32 "
        "{%0,%1,%2,%3}, {%4,%5,%6,%7}, {%8,%9}, {%0,%1,%2,%3};"
        : "+f"(c[0]), "+f"(c[1]), "+f"(c[2]), "+f"(c[3])
        : "r"(a[0]), "r"(a[1]), "r"(a[2]), "r"(a[3]), "r"(b0), "r"(b1));
}
__device__ __forceinline__ uint32_t swz(uint32_t off) { return off ^ ((off >> 3) & 0x70); }

// address for ldmatrix.x4.trans over a [row][64 halves] swizzled tile
__device__ __forceinline__ uint32_t trans_addr(uint32_t base, int kk, int colhalf, int lane) {
    int mat = lane >> 3, r = lane & 7;
    int lrow = kk * 16 + ((mat & 2) << 2) + r;
    int cb = colhalf * 2 + ((mat & 1) << 4);
    return base + swz((uint32_t)lrow * 128 + cb);
}

// ================= merged fp32 -> fp16 convert (x + 4 weights) =================
// blocks [0,16384): x ; [16384, 16384+4*1024): weights
__global__ void convert_all(const float* __restrict__ x,
                            const float* __restrict__ w0, const float* __restrict__ w1,
                            const float* __restrict__ w2s, const float* __restrict__ w3,
                            __half* __restrict__ x2, __half* __restrict__ wout)
{
    int bid = blockIdx.x;
    const float* in;
    __half* out;
    int idx;
    if (bid < 16384) {
        in = x; out = g_x2;   // == x2
        idx = bid * 256 + threadIdx.x;
    } else {
        int wb = bid - 16384;
        int seg = wb >> 10;
        in = (seg == 0) ? w0 : (seg == 1) ? w1 : (seg == 2) ? w2s : w3;
        out = wout + (size_t)seg * E_ * KTOT;
        idx = (wb & 1023) * 256 + threadIdx.x;
    }
    float4 v = *(const float4*)&in[(size_t)idx * 4];
    union { __half b[4]; uint2 u; } Hh;
    Hh.b[0] = __float2half_rn(v.x);
    Hh.b[1] = __float2half_rn(v.y);
    Hh.b[2] = __float2half_rn(v.z);
    Hh.b[3] = __float2half_rn(v.w);
    *(uint2*)&out[(size_t)idx * 4] = Hh.u;
}

// ================= HMMA GEMM =================
// Tile 128x128x64, 8 warps, warp tile 64x32, mma.sync m16n8k16.
#define GBM 128
#define GBN 128
#define SLAB 64                 // fp16 K per slab = 128 bytes per row
#define NSLAB (KTOT/SLAB)       // 16
#define NSTG 3
#define AB_BYTES (GBM*128)      // 16384 (A tile == B tile size)
#define STG_BYTES (2*AB_BYTES)  // 32768
#define GEMM_DSMEM (NSTG*STG_BYTES + 1024)

__device__ __forceinline__ void gemm_issue_loads(
    const __half* ga, const __half* gw,
    uint32_t base, int slab, int buf, int t)
{
    int k0 = slab * SLAB;
    uint32_t stA = base + buf * STG_BYTES;
    uint32_t stW = stA + AB_BYTES;
    const __half* gak = ga + k0;
    const __half* gwk = gw + k0;
    #pragma unroll
    for (int j = 0; j < 4; j++) {
        int i = t + j * 256;            // 0..1023
        int row = i >> 3, c = i & 7;
        cp_async16(stA + swz(row * 128 + c * 16), gak + (size_t)row * KTOT + c * 8);
    }
    #pragma unroll
    for (int j = 0; j < 4; j++) {
        int i = t + j * 256;
        int row = i >> 3, c = i & 7;
        cp_async16(stW + swz(row * 128 + c * 16), gwk + (size_t)row * KTOT + c * 8);
    }
    cp_commit();
}

struct GemmFrag { float acc[4][4][4]; };

__device__ __forceinline__ void gemm_mainloop(
    const __half* ga, const __half* gw, uint32_t base, int t, GemmFrag& F)
{
    const int wid = t >> 5, lane = t & 31;
    const int wm = wid >> 2;
    const int wn = wid & 3;
    #pragma unroll
    for (int mi = 0; mi < 4; mi++)
        #pragma unroll
        for (int ni = 0; ni < 4; ni++)
            #pragma unroll
            for (int r = 0; r < 4; r++) F.acc[mi][ni][r] = 0.f;

    #pragma unroll
    for (int s = 0; s < NSTG - 1; s++) gemm_issue_loads(ga, gw, base, s, s, t);

    const int lrow = lane & 15;
    const int lhalf = (lane >> 4) * 16;

    for (int i = 0; i < NSLAB; i++) {
        cp_wait_group<NSTG - 2>();
        __syncthreads();
        if (i + NSTG - 1 < NSLAB)
            gemm_issue_loads(ga, gw, base, i + NSTG - 1, (i + NSTG - 1) % NSTG, t);
        else
            cp_commit();

        uint32_t sA = base + (i % NSTG) * STG_BYTES;
        uint32_t sB = sA + AB_BYTES;

        #pragma unroll
        for (int kk = 0; kk < 4; kk++) {
            uint32_t a[4][4], b[2][4];
            #pragma unroll
            for (int mi = 0; mi < 4; mi++) {
                uint32_t off = (uint32_t)(wm * 64 + mi * 16 + lrow) * 128 + kk * 32 + lhalf;
                ldmatrix_x4(a[mi], sA + swz(off));
            }
            #pragma unroll
            for (int nb = 0; nb < 2; nb++) {
                uint32_t off = (uint32_t)(wn * 32 + nb * 16 + lrow) * 128 + kk * 32 + lhalf;
                ldmatrix_x4(b[nb], sB + swz(off));
            }
            #pragma unroll
            for (int mi = 0; mi < 4; mi++)
                #pragma unroll
                for (int ni = 0; ni < 4; ni++) {
                    int nb = ni >> 1, hi = ni & 1;
                    mma_fp16(F.acc[mi][ni], a[mi], b[nb][hi], b[nb][hi + 2]);
                }
        }
        __syncthreads();
    }
}

// fp32 epilogue (Wo output)
__device__ __forceinline__ void gemm_epilogue_f32(
    GemmFrag& F, const float* bias, float* C, int bm, int cn, int t)
{
    const int wid = t >> 5, lane = t & 31;
    const int wm = wid >> 2, wn = wid & 3;
    const int qrow = lane >> 2;
    const int qcol = (lane & 3) * 2;
    #pragma unroll
    for (int mi = 0; mi < 4; mi++) {
        int row0 = bm + wm * 64 + mi * 16 + qrow;
        #pragma unroll
        for (int ni = 0; ni < 4; ni++) {
            int col = cn + wn * 32 + ni * 8 + qcol;
            float2 bb = *(const float2*)&bias[col];
            *(float2*)&C[(size_t)row0 * E_ + col] =
                make_float2(F.acc[mi][ni][0] + bb.x, F.acc[mi][ni][1] + bb.y);
            *(float2*)&C[(size_t)(row0 + 8) * E_ + col] =
                make_float2(F.acc[mi][ni][2] + bb.x, F.acc[mi][ni][3] + bb.y);
        }
    }
}

// fp16 epilogue (q/k/v outputs)
__device__ __forceinline__ void gemm_epilogue_f16(
    GemmFrag& F, const float* bias, __half* C, int bm, int cn, bool relu, int t)
{
    const int wid = t >> 5, lane = t & 31;
    const int wm = wid >> 2, wn = wid & 3;
    const int qrow = lane >> 2;
    const int qcol = (lane & 3) * 2;
    #pragma unroll
    for (int mi = 0; mi < 4; mi++) {
        int row0 = bm + wm * 64 + mi * 16 + qrow;
        #pragma unroll
        for (int ni = 0; ni < 4; ni++) {
            int col = cn + wn * 32 + ni * 8 + qcol;
            float2 bb = *(const float2*)&bias[col];
            float v0 = F.acc[mi][ni][0] + bb.x;
            float v1 = F.acc[mi][ni][1] + bb.y;
            float v2 = F.acc[mi][ni][2] + bb.x;
            float v3 = F.acc[mi][ni][3] + bb.y;
            if (relu) {
                v0 = fmaxf(v0, 0.f); v1 = fmaxf(v1, 0.f);
                v2 = fmaxf(v2, 0.f); v3 = fmaxf(v3, 0.f);
            }
            __half2 p01 = __floats2half2_rn(v0, v1);
            __half2 p23 = __floats2half2_rn(v2, v3);
            *(__half2*)&C[(size_t)row0 * E_ + col]       = p01;
            *(__half2*)&C[(size_t)(row0 + 8) * E_ + col] = p23;
        }
    }
}

// Merged Q/K/V projection: W2all = [Wq2; Wk2; Wv2] rows 0..3071
__global__ __launch_bounds__(256, 2)
void gemm_qkv(const __half* __restrict__ A2, const __half* __restrict__ W2all,
              const float* __restrict__ bq, const float* __restrict__ bk,
              const float* __restrict__ bv,
              __half* __restrict__ qp, __half* __restrict__ kp, __half* __restrict__ vp)
{
    extern __shared__ char dsm[];
    const int t = threadIdx.x;
    const int bm = blockIdx.y * GBM;
    const int bnG = blockIdx.x * GBN;          // 0..2944
    const int seg = bnG >> 10;                 // 0=q 1=k 2=v
    const int cn = bnG & 1023;

    uint32_t base = (smem_u32(dsm) + 1023u) & ~1023u;
    const __half* ga = A2 + (size_t)bm * KTOT;
    const __half* gw = W2all + (size_t)bnG * KTOT;

    GemmFrag F;
    gemm_mainloop(ga, gw, base, t, F);

    const float* bias = (seg == 0) ? bq : (seg == 1) ? bk : bv;
    __half* C = (seg == 0) ? qp : (seg == 1) ? kp : vp;
    gemm_epilogue_f16(F, bias, C, bm, cn, seg < 2, t);
}

// Single-output GEMM (used for Wo)
__global__ __launch_bounds__(256, 2)
void gemm_mma(const __half* __restrict__ A2, const __half* __restrict__ W2,
              const float* __restrict__ bias, float* __restrict__ C)
{
    extern __shared__ char dsm[];
    const int t = threadIdx.x;
    const int bm = blockIdx.y * GBM;
    const int bn = blockIdx.x * GBN;

    uint32_t base = (smem_u32(dsm) + 1023u) & ~1023u;
    const __half* ga = A2 + (size_t)bm * KTOT;
    const __half* gw = W2 + (size_t)bn * KTOT;

    GemmFrag F;
    gemm_mainloop(ga, gw, base, t, F);
    gemm_epilogue_f32(F, bias, C, bm, bn, t);
}

// ================= kv via HMMA (ldmatrix.trans, zero staging) =================
__global__ __launch_bounds__(256, 2)
void kv_hmma(const __half* __restrict__ k, const __half* __restrict__ v)
{
    __shared__ __align__(16) __half Ksm[2][64 * 64];
    __shared__ __align__(16) __half Vsm[2][64 * 64];
    __shared__ __half2 wsin[KVCH / 2], wcos[KVCH / 2];   // 128 pairs each

    const int t = threadIdx.x;
    const int wid = t >> 5, lane = t & 31;
    const int head = blockIdx.x, chunk = blockIdx.y;
    const int b = head / H_, h = head % H_;

    if (t < KVCH / 2) {
        int l0 = chunk * KVCH + t * 2;
        float s0, c0, s1, c1;
        sincosf((float)M_PI * 0.5f * (float)(l0 + 1) / (float)L_, &s0, &c0);
        sincosf((float)M_PI * 0.5f * (float)(l0 + 2) / (float)L_, &s1, &c1);
        wsin[t] = __floats2half2_rn(s0, s1);
        wcos[t] = __floats2half2_rn(c0, c1);
    }

    const __half* kbase = k + ((size_t)(b * L_ + chunk * KVCH)) * E_ + h * HD_;
    const __half* vbase = v + ((size_t)(b * L_ + chunk * KVCH)) * E_ + h * HD_;

    auto issue = [&](int slab, int buf) {
        uint32_t sK = smem_u32(Ksm[buf]);
        uint32_t sV = smem_u32(Vsm[buf]);
        #pragma unroll
        for (int j = 0; j < 4; j++) {
            int i = t + j * 256;            // 0..1023: first 512 = k, next = v
            int idx = i & 511;
            int row = idx >> 3, c = idx & 7;
            const __half* src = ((i >> 9) ? vbase : kbase)
                              + (size_t)(slab * 64 + row) * E_ + c * 8;
            uint32_t dst = ((i >> 9) ? sV : sK) + swz((uint32_t)row * 128 + c * 16);
            cp_async16(dst, src);
        }
        cp_commit();
    };

    float acc[9][4];
    #pragma unroll
    for (int n8 = 0; n8 < 9; n8++)
        #pragma unroll
        for (int r = 0; r < 4; r++) acc[n8][r] = 0.f;

    issue(0, 0);
    const uint32_t ONES = 0x3C003C00u;
    const int d0 = (wid & 3) * 16;

    #pragma unroll
    for (int slab = 0; slab < KVCH / 64; slab++) {     // 4
        if (slab + 1 < KVCH / 64) {
            issue(slab + 1, (slab + 1) & 1);
            cp_wait_group<1>();
        } else {
            cp_wait_group<0>();
        }
        __syncthreads();
        uint32_t sK = smem_u32(Ksm[slab & 1]);
        uint32_t sV = smem_u32(Vsm[slab & 1]);
        const __half2* wsel = (wid < 4) ? wsin : wcos;
        #pragma unroll
        for (int kk = 0; kk < 4; kk++) {
            uint32_t a[4], bf[4][4];
            ldmatrix_x4_trans(a, trans_addr(sK, kk, d0, lane));
            #pragma unroll
            for (int nb = 0; nb < 4; nb++)
                ldmatrix_x4_trans(bf[nb], trans_addr(sV, kk, nb * 16, lane));
            __half2 w0 = wsel[slab * 32 + kk * 8 + (lane & 3)];
            __half2 w1 = wsel[slab * 32 + kk * 8 + (lane & 3) + 4];
            __half2* ah = (__half2*)a;
            ah[0] = __hmul2(ah[0], w0);
            ah[1] = __hmul2(ah[1], w0);
            ah[2] = __hmul2(ah[2], w1);
            ah[3] = __hmul2(ah[3], w1);
            #pragma unroll
            for (int n8 = 0; n8 < 8; n8++)
                mma_fp16(acc[n8], a, bf[n8 >> 1][n8 & 1], bf[n8 >> 1][(n8 & 1) + 2]);
            mma_fp16(acc[8], a, ONES, ONES);
        }
        __syncthreads();
    }

    // epilogue: fp16 partial kv + fp32 ksum partial
    const int qr = lane >> 2, qc = (lane & 3) * 2;
    __half* kvout = g_kvph + ((size_t)(chunk * BH_ + head)) * 128 * HD_;
    #pragma unroll
    for (int n8 = 0; n8 < 8; n8++) {
        int col = n8 * 8 + qc;
        __half2 p01 = __floats2half2_rn(acc[n8][0], acc[n8][1]);
        __half2 p23 = __floats2half2_rn(acc[n8][2], acc[n8][3]);
        *(__half2*)&kvout[(wid * 16 + qr) * HD_ + col]     = p01;
        *(__half2*)&kvout[(wid * 16 + qr + 8) * HD_ + col] = p23;
    }
    if ((lane & 3) == 0) {
        g_ksump[(chunk * BH_ + head) * 128 + wid * 16 + qr]     = acc[8][0];
        g_ksump[(chunk * BH_ + head) * 128 + wid * 16 + qr + 8] = acc[8][2];
    }
}

// Reduce fp16 partials; emit transposed fp16 kv.
// grid (BH_, 8): slice = 16 d' rows (1024 elems). half2 reads, smem transpose.
__global__ __launch_bounds__(256)
void kv_reduce()
{
    __shared__ float buf[16][65];
    const int head = blockIdx.x, slice = blockIdx.y;
    const int t = threadIdx.x;

    // accumulate: 1024 elems = 512 half2 pairs, coalesced vector reads
    #pragma unroll
    for (int j = 0; j < 2; j++) {
        int p = t + j * 256;                // 0..511
        int el = p * 2;                     // 0..1022
        int e = slice * 1024 + el;
        float2 s = make_float2(0.f, 0.f);
        #pragma unroll
        for (int c = 0; c < NCHUNK; c++) {
            __half2 hv = *(const __half2*)&g_kvph[((size_t)(c * BH_ + head)) * 128 * HD_ + e];
            float2 f = __half22float2(hv);
            s.x += f.x; s.y += f.y;
        }
        int dl = el >> 6, m = el & 63;      // local d' row, m pair start
        buf[dl][m]     = s.x;
        buf[dl][m + 1] = s.y;
    }
    __syncthreads();

    // write: g_kvt[head][slab][m][d&63]; slice covers d' = slice*16..+15
    const int d_base = slice * 16;
    const int slab = d_base >> 6;
    const int dmod = d_base & 63;
    __half* outp = g_kvt + (((size_t)head * 2 + slab) * 64) * 64;
    #pragma unroll
    for (int j = 0; j < 2; j++) {
        int o = t + j * 256;                // 0..511 half2 slots
        int m = o >> 3, d2 = o & 7;         // 8 half2 = 16 d per m-row
        __half2 hv = __floats2half2_rn(buf[d2 * 2][m], buf[d2 * 2 + 1][m]);
        *(__half2*)&outp[m * 64 + dmod + d2 * 2] = hv;
    }

    if (slice == 0 && t < 128) {
        float s = 0.f;
        #pragma unroll
        for (int c = 0; c < NCHUNK; c++)
            s += g_ksump[(c * BH_ + head) * 128 + t];
        g_ksum[head * 128 + t] = s;
    }
}

// ================= attn via HMMA =================
// A = q_ fp16 1-term (2 slabs of k64), B = kvt single-term (2 slabs).
// Passes: (A0,B0)(A1,B1) = sum over d' of q_ * kv.
#define ATT_A_SM 32768            // 2 slabs * 128 rows * 128B
#define ATT_B_SM 16384            // 2 slabs * 64 rows * 128B
#define ATT_DSMEM (ATT_A_SM + ATT_B_SM + 128)

__global__ __launch_bounds__(256, 2)
void attn_hmma(const __half* __restrict__ q)
{
    extern __shared__ char dsm[];
    __shared__ float ss[128], cs[128], zs[128], ks_s[128];

    const int t = threadIdx.x;
    const int wid = t >> 5, lane = t & 31;
    const int ltile = blockIdx.x;           // 0..31
    const int head  = blockIdx.y;           // 0..63
    const int b = head / H_, h = head % H_;

    char* sm = (char*)((((uintptr_t)dsm) + 127) & ~(uintptr_t)127);
    uint32_t sA = smem_u32(sm);
    uint32_t sB = sA + ATT_A_SM;

    if (t < 128) {
        int l = ltile * 128 + t;
        float ang = (float)M_PI * 0.5f * (float)(l + 1) / (float)L_;
        sincosf(ang, &ss[t], &cs[t]);
        ks_s[t] = g_ksum[head * 128 + t];
    }

    {
        const __half* kvt = g_kvt + (size_t)head * 128 * 64;
        #pragma unroll
        for (int j = 0; j < 4; j++) {
            int i = t + j * 256;            // 0..1023 16B chunks
            int row = i >> 3, c = i & 7;    // 128 rows of 64 halves
            cp_async16(sB + swz((uint32_t)row * 128 + c * 16),
                       kvt + row * 64 + c * 8);
        }
        cp_commit();
    }
    __syncthreads();

    {
        const int l_loc = t >> 1;           // 0..127
        const int halfsel = t & 1;
        int lg = ltile * 128 + l_loc;
        const __half* qrow = q + ((size_t)(b * L_ + lg)) * E_ + h * HD_;
        float w = halfsel ? cs[l_loc] : ss[l_loc];
        float zpart = 0.f;
        char* aw = sm + halfsel * 16384;    // slab halfsel
        #pragma unroll 4
        for (int it = 0; it < 32; it++) {
            int dp = halfsel * 64 + 2 * it;
            float2 qq = __half22float2(*(const __half2*)&qrow[dp & 63]);
            float f0 = w * qq.x, f1 = w * qq.y;
            zpart += f0 * ks_s[dp] + f1 * ks_s[dp + 1];
            __half2 Hp = __floats2half2_rn(f0, f1);
            uint32_t off = swz((uint32_t)l_loc * 128 + (dp & 63) * 2);
            *(uint32_t*)(aw + off) = *(uint32_t*)&Hp;
        }
        zpart += __shfl_xor_sync(0xffffffffu, zpart, 1);
        if (!halfsel) zs[l_loc] = 1.f / fmaxf(zpart, EPS_);
    }

    cp_wait_group<0>();
    __syncthreads();

    const int wm = wid & 1;
    const int wn = wid >> 1;
    const int lrow = lane & 15;
    const int lhalf = (lane >> 4) * 16;

    float acc[4][2][4];
    #pragma unroll
    for (int mi = 0; mi < 4; mi++)
        #pragma unroll
        for (int hi = 0; hi < 2; hi++)
            #pragma unroll
            for (int r = 0; r < 4; r++) acc[mi][hi][r] = 0.f;

    #pragma unroll
    for (int p = 0; p < 2; p++) {
        uint32_t a_s = sA + p * 16384;
        uint32_t b_s = sB + p * 8192;
        #pragma unroll
        for (int kk = 0; kk < 4; kk++) {
            uint32_t a[4][4], bfr[4];
            #pragma unroll
            for (int mi = 0; mi < 4; mi++) {
                uint32_t off = (uint32_t)(wm * 64 + mi * 16 + lrow) * 128 + kk * 32 + lhalf;
                ldmatrix_x4(a[mi], a_s + swz(off));
            }
            {
                uint32_t off = (uint32_t)(wn * 16 + lrow) * 128 + kk * 32 + lhalf;
                ldmatrix_x4(bfr, b_s + swz(off));
            }
            #pragma unroll
            for (int mi = 0; mi < 4; mi++)
                #pragma unroll
                for (int hi = 0; hi < 2; hi++)
                    mma_fp16(acc[mi][hi], a[mi], bfr[hi], bfr[hi + 2]);
        }
    }

    const int qr = lane >> 2;
    const int qc = (lane & 3) * 2;
    #pragma unroll
    for (int mi = 0; mi < 4; mi++) {
        #pragma unroll
        for (int hi = 0; hi < 2; hi++) {
            #pragma unroll
            for (int r = 0; r < 2; r++) {
                int lloc = wm * 64 + mi * 16 + qr + r * 8;
                int n = wn * 16 + hi * 8 + qc;
                float z = zs[lloc];
                __half2 Hp = __floats2half2_rn(acc[mi][hi][r * 2 + 0] * z,
                                               acc[mi][hi][r * 2 + 1] * z);
                __half* ob = g_attn2 + ((size_t)(b * L_ + ltile * 128 + lloc)) * KTOT
                           + h * HD_ + n;
                *(uint32_t*)(ob) = *(uint32_t*)&Hp;
            }
        }
    }
}

// ================= launcher =================
extern "C" void kernel_launch(void* const* d_in, const int* in_sizes, int n_in,
                              void* d_out, int out_size)
{
    const float* x  = (const float*)d_in[0];
    const float* Wq = (const float*)d_in[1];
    const float* bq = (const float*)d_in[2];
    const float* Wk = (const float*)d_in[3];
    const float* bk = (const float*)d_in[4];
    const float* Wv = (const float*)d_in[5];
    const float* bv = (const float*)d_in[6];
    const float* Wo = (const float*)d_in[7];
    const float* bo = (const float*)d_in[8];
    float* out = (float*)d_out;

    __half *x2, *attn2, *w2, *qh, *kh, *vh;
    cudaGetSymbolAddress((void**)&x2,    g_x2);
    cudaGetSymbolAddress((void**)&attn2, g_attn2);
    cudaGetSymbolAddress((void**)&w2,    g_w2);
    cudaGetSymbolAddress((void**)&qh,    g_qh);
    cudaGetSymbolAddress((void**)&kh,    g_kh);
    cudaGetSymbolAddress((void**)&vh,    g_vh);
    __half* w2o = w2 + (size_t)3 * E_ * KTOT;

    cudaFuncSetAttribute(gemm_mma,  cudaFuncAttributeMaxDynamicSharedMemorySize, GEMM_DSMEM);
    cudaFuncSetAttribute(gemm_qkv,  cudaFuncAttributeMaxDynamicSharedMemorySize, GEMM_DSMEM);
    cudaFuncSetAttribute(attn_hmma, cudaFuncAttributeMaxDynamicSharedMemorySize, ATT_DSMEM);

    // one merged conversion launch: x + 4 weights
    convert_all<<<16384 + 4096, 256>>>(x, Wq, Wk, Wv, Wo, x2, w2);

    // merged QKV projection (fp16 outputs)
    gemm_qkv<<<dim3(3 * E_ / GBN, M_ / GBM), 256, GEMM_DSMEM>>>(
        x2, w2, bq, bk, bv, qh, kh, vh);

    kv_hmma<<<dim3(BH_, NCHUNK), 256>>>(kh, vh);
    kv_reduce<<<dim3(BH_, 8), 256>>>();
    attn_hmma<<<dim3(32, BH_), 256, ATT_DSMEM>>>(qh);

    gemm_mma<<<dim3(E_ / GBN, M_ / GBM), 256, GEMM_DSMEM>>>(attn2, w2o, bo, out);
}